// round 14
// baseline (speedup 1.0000x reference)
#include <cuda_runtime.h>
#include <cstdint>
#include <cstddef>
typedef unsigned long long ull;

__device__ float g_states[2*32*16*64*64];
__device__ float g_R[2*32*16*64*64];
__device__ float g_eA[1024*64];
__device__ float g_expsA[32*32];
__device__ float g_yd[2*2048*1024];     // Y_diag, then += e*C.R^T (SSD total)
__device__ unsigned g_cnt1;             // chunk-done counter (reset by add kernel)
__device__ unsigned g_cnt2;             // scan-done counter

__device__ __forceinline__ void cp_async16(float* dst, const float* src) {
    unsigned s = (unsigned)__cvta_generic_to_shared(dst);
    asm volatile("cp.async.cg.shared.global [%0], [%1], 16;\n" :: "r"(s), "l"(src));
}
__device__ __forceinline__ void cp_commit() { asm volatile("cp.async.commit_group;\n"); }
__device__ __forceinline__ void cp_wait1()  { asm volatile("cp.async.wait_group 1;\n" ::: "memory"); }
__device__ __forceinline__ void cp_wait0()  { asm volatile("cp.async.wait_group 0;\n" ::: "memory"); }
__device__ __forceinline__ ull f2fma(ull a, ull b, ull c) {
    ull d; asm("fma.rn.f32x2 %0, %1, %2, %3;" : "=l"(d) : "l"(a), "l"(b), "l"(c)); return d;
}
__device__ __forceinline__ ull f2mul(ull a, ull b) {
    ull d; asm("mul.rn.f32x2 %0, %1, %2;" : "=l"(d) : "l"(a), "l"(b)); return d;
}
__device__ __forceinline__ ull f2add(ull a, ull b) {
    ull d; asm("add.rn.f32x2 %0, %1, %2;" : "=l"(d) : "l"(a), "l"(b)); return d;
}
__device__ __forceinline__ ull pk2(float lo, float hi) {
    ull r; asm("mov.b64 %0, {%1, %2};" : "=l"(r) : "f"(lo), "f"(hi)); return r;
}
__device__ __forceinline__ float2 upk2(ull p) {
    float2 f; asm("mov.b64 {%0, %1}, %2;" : "=f"(f.x), "=f"(f.y) : "l"(p)); return f;
}
__device__ __forceinline__ int swz_chunk(int c) { return ((c & 7) << 1) | (c >> 3); }
__device__ __forceinline__ int swz_pos(int j)   { return (swz_chunk(j >> 2) << 2) | (j & 3); }

#define BAR_ALL()  asm volatile("bar.sync 1, 256;" ::: "memory")
#define BAR_PROD() asm volatile("bar.sync 2, 128;" ::: "memory")
#define BAR_HELP() asm volatile("bar.sync 3, 128;" ::: "memory")

#define OFF_DL 20480
#define OFF_DK 22528
#define OFF_NW 22544
#define OFF_C2 24592
#define OFF_WT 26640
#define WKV_SMEM_FLOATS 26768

__device__ __forceinline__ void wkv_precompute(int wn, int tid, float* sm)
{
    if (tid >= 64) return;
    const int j = tid, pj = swz_pos(j);
    const float* pr = sm + (wn & 3) * 5120;
    float* nw = sm + OFF_NW + (wn & 1) * 1024;
    float* c2 = sm + OFF_C2 + (wn & 1) * 1024;
    float W = 1.f;
#pragma unroll
    for (int t = 0; t < 16; ++t) {
        nw[t * 64 + j] = -W;
        W *= pr[3072 + t * 64 + j];
        c2[t * 64 + j] = __fdividef(pr[4096 + t * 64 + j] * pr[1024 + t * 64 + pj], W);
    }
    sm[OFF_WT + (wn & 1) * 64 + j] = W;
}

// Software-pipelined producer: per step the CHAIN is only the cheap u-dot path;
// the full dot P = S~·k_next is computed off-chain (result needed next step).
//   full_t = P_t + c_{t-1}*(δ_{t-1}·k_t),  δ_t = v_t + nW_t*full_t
//   S~ += c_{t-1}·δ_{t-1}  (folded at step t, fused with the u-dot)
// Window boundary: S2 *= wt, c_prev *= wt; next window prologue recomputes P.
__device__ __forceinline__ void wkv_producer(int tid, float* sm)
{
    const int i = tid >> 1, h2 = tid & 1;
    const int pos_i = swz_pos(i);
    ull S2[16];
#pragma unroll
    for (int u = 0; u < 16; ++u) S2[u] = 0ull;
    float c_prev = 0.f;
    float P = 0.f;
    const float* dprev = sm + OFF_DL + 1024 + 15 * 64;   // zeroed bootstrap row

#pragma unroll 1
    for (int win = 0; win < 128; ++win) {
        const float* pr = sm + (win & 3) * 5120;
        float* dl = sm + OFF_DL + (win & 1) * 1024;
        const float* nw = sm + OFF_NW + (win & 1) * 1024;
        const float* c2 = sm + OFF_C2 + (win & 1) * 1024;

        ull kt[16];
        // ---- window prologue: load k0, P = S2·k0 (S2 = scaled, pre-fold) ----
        {
            const float* k0s = pr + 1024;
#pragma unroll
            for (int u = 0; u < 8; ++u) {
                float4 q = *(const float4*)(k0s + (2 * u + h2) * 4);
                kt[2*u] = *(ull*)&q.x; kt[2*u+1] = *(ull*)&q.z;
            }
            ull a0 = f2mul(S2[0], kt[0]);
            ull a1 = f2mul(S2[1], kt[1]);
            ull a2 = f2mul(S2[2], kt[2]);
            ull a3 = f2mul(S2[3], kt[3]);
#pragma unroll
            for (int u = 1; u < 4; ++u) {
                a0 = f2fma(S2[4*u+0], kt[4*u+0], a0);
                a1 = f2fma(S2[4*u+1], kt[4*u+1], a1);
                a2 = f2fma(S2[4*u+2], kt[4*u+2], a2);
                a3 = f2fma(S2[4*u+3], kt[4*u+3], a3);
            }
            a0 = f2add(a0, a1); a2 = f2add(a2, a3); a0 = f2add(a0, a2);
            float2 af = upk2(a0);
            P = af.x + af.y;
            P += __shfl_xor_sync(0xffffffffu, P, 1);
        }

#pragma unroll 1
        for (int st = 0; st < 16; ++st) {
            // ---- chain: fold δ_prev (S2 += c_prev·δ_prev) fused with u-dot ----
            const ull cp2 = pk2(c_prev, c_prev);
            ull u0 = 0ull, u1 = 0ull, u2 = 0ull, u3 = 0ull;
#pragma unroll
            for (int q = 0; q < 8; ++q) {
                float4 dq = *(const float4*)(dprev + (2 * q + h2) * 4);
                ull t0 = *(ull*)&dq.x, t1 = *(ull*)&dq.z;
                if (q & 1) { u2 = f2fma(t0, kt[2*q], u2); u3 = f2fma(t1, kt[2*q+1], u3); }
                else       { u0 = f2fma(t0, kt[2*q], u0); u1 = f2fma(t1, kt[2*q+1], u1); }
                S2[2*q]   = f2fma(cp2, t0, S2[2*q]);
                S2[2*q+1] = f2fma(cp2, t1, S2[2*q+1]);
            }
            u0 = f2add(u0, u1); u2 = f2add(u2, u3); u0 = f2add(u0, u2);
            float2 uf = upk2(u0);
            float uu = uf.x + uf.y;
            uu += __shfl_xor_sync(0xffffffffu, uu, 1);

            const float full = fmaf(c_prev, uu, P);
            const float dlt = fmaf(nw[st*64 + i], full, pr[2048 + st*64 + i]);
            dl[st*64 + pos_i] = dlt;
            c_prev = c2[st*64 + i];
            dprev = dl + st*64;

            if (st < 15) {
                // ---- off-chain: load k_{st+1} (overwrite kt), P = S2·k_next ----
                const float* kns = pr + 1024 + (st + 1) * 64;
#pragma unroll
                for (int u = 0; u < 8; ++u) {
                    float4 q = *(const float4*)(kns + (2 * u + h2) * 4);
                    kt[2*u] = *(ull*)&q.x; kt[2*u+1] = *(ull*)&q.z;
                }
                ull a0 = f2mul(S2[0], kt[0]);
                ull a1 = f2mul(S2[1], kt[1]);
                ull a2 = f2mul(S2[2], kt[2]);
                ull a3 = f2mul(S2[3], kt[3]);
#pragma unroll
                for (int u = 1; u < 4; ++u) {
                    a0 = f2fma(S2[4*u+0], kt[4*u+0], a0);
                    a1 = f2fma(S2[4*u+1], kt[4*u+1], a1);
                    a2 = f2fma(S2[4*u+2], kt[4*u+2], a2);
                    a3 = f2fma(S2[4*u+3], kt[4*u+3], a3);
                }
                a0 = f2add(a0, a1); a2 = f2add(a2, a3); a0 = f2add(a0, a2);
                float2 af = upk2(a0);
                P = af.x + af.y;
                P += __shfl_xor_sync(0xffffffffu, P, 1);
                BAR_PROD();
            } else {
                // ---- window epilogue: rescale deferred state + carry ----
                const float wti = sm[OFF_WT + (win & 1) * 64 + i];
                const ull w2 = pk2(wti, wti);
#pragma unroll
                for (int u = 0; u < 16; ++u) S2[u] = f2mul(S2[u], w2);
                c_prev *= wti;
                BAR_ALL();
            }
        }
    }
}

__device__ __forceinline__ void wkv_emit_window(
    int wn, int tid, float* sm, float* __restrict__ out, int b, int h)
{
    const float* pr = sm + (wn & 3) * 5120;
    const float* dl = sm + OFF_DL + (wn & 1) * 1024;
    float* s_dk = sm + OFF_DK;
    const int lane = tid & 31, wid = tid >> 5;
#pragma unroll
    for (int rep = 0; rep < 4; ++rep) {
        const int st = rep * 4 + wid;
        const int pp = swz_chunk(lane >> 1) * 4 + (lane & 1) * 2;
        float2 kv  = *(const float2*)(pr + 1024 + st * 64 + pp);
        float2 dl2 = *(const float2*)(dl + st * 64 + pp);
        float pd = fmaf(dl2.x, kv.x, dl2.y * kv.y);
#pragma unroll
        for (int off = 16; off > 0; off >>= 1)
            pd += __shfl_xor_sync(0xffffffffu, pd, off);
        if (lane == 0) s_dk[st] = pd;
    }
    BAR_HELP();
#pragma unroll
    for (int rep = 0; rep < 4; ++rep) {
        const int idx = rep * 128 + tid;
        const int st = idx >> 5, cp2 = idx & 31;
        const int col = cp2 * 2;
        const int pp = swz_chunk(cp2 >> 1) * 4 + (cp2 & 1) * 2;
        float2 dv = *(const float2*)(dl + st * 64 + pp);
        float2 k_ = *(const float2*)(pr + 1024 + st * 64 + pp);
        float2 r_ = *(const float2*)(pr + st * 64 + col);
        float2 v_ = *(const float2*)(pr + 2048 + st * 64 + col);
        float2 w_ = *(const float2*)(pr + 3072 + st * 64 + col);
        float2 b_ = *(const float2*)(pr + 4096 + st * 64 + col);
        const float dk = s_dk[st];
        float2 y;
        y.x = r_.x * fmaf(b_.x * k_.x, dk, w_.x * (v_.x - dv.x));
        y.y = r_.y * fmaf(b_.y * k_.y, dk, w_.y * (v_.y - dv.y));
        *(float2*)(out + (size_t)(b * 2048 + wn * 16 + st) * 1024 + h * 64 + col) = y;
    }
}

__device__ __forceinline__ void wkv_helper(
    int tid, float* sm, const float* const* arrs, size_t base,
    float* __restrict__ out, int b, int h)
{
#pragma unroll 1
    for (int win = 0; win < 128; ++win) {
        if (win + 2 < 128) {
            const int dst = ((win + 2) & 3) * 5120;
#pragma unroll
            for (int a = 0; a < 5; ++a)
#pragma unroll
                for (int rep = 0; rep < 2; ++rep) {
                    int x = rep * 128 + tid;
                    int st = x >> 4, c = x & 15;
                    int dc = (a == 1) ? swz_chunk(c) : c;
                    cp_async16(&sm[dst + a * 1024 + st * 64 + dc * 4],
                               arrs[a] + base + (size_t)((win + 2) * 16 + st) * 64 + c * 4);
                }
            cp_commit();
        }
        if (win >= 1) wkv_emit_window(win - 1, tid, sm, out, b, h);
        if (win >= 126) cp_wait0(); else cp_wait1();
        BAR_HELP();   // fence all helpers' retired cp.async before cross-reads
        if (win + 1 < 128) wkv_precompute(win + 1, tid, sm);
        BAR_ALL();
    }
    wkv_emit_window(127, tid, sm, out, b, h);
}

__device__ __forceinline__ void wkv_block(
    int bh, int tid, float* sm,
    const float* __restrict__ rr, const float* __restrict__ kk_g,
    const float* __restrict__ vv_g, const float* __restrict__ ww_g,
    const float* __restrict__ bo_g, float* __restrict__ out)
{
    const int b = bh >> 4, h = bh & 15;
    const size_t base = (size_t)bh * 2048 * 64;
    const float* arrs[5] = { rr, kk_g, vv_g, ww_g, bo_g };
#pragma unroll
    for (int wv = 0; wv < 2; ++wv)
#pragma unroll
        for (int a = 0; a < 5; ++a) {
            int st = tid >> 4, c = tid & 15;
            int dc = (a == 1) ? swz_chunk(c) : c;
            cp_async16(&sm[wv * 5120 + a * 1024 + st * 64 + dc * 4],
                       arrs[a] + base + (size_t)(wv * 16 + st) * 64 + c * 4);
        }
    cp_commit();
    // zero both dl buffers (bootstrap: first fold reads zeros, c_prev=0)
#pragma unroll
    for (int x = 0; x < 8; ++x) sm[OFF_DL + x * 256 + tid] = 0.f;
    cp_wait0();
    BAR_ALL();
    if (tid >= 128) wkv_precompute(0, tid - 128, sm);
    BAR_ALL();
    if (tid < 128) wkv_producer(tid, sm);
    else           wkv_helper(tid - 128, sm, arrs, base, out, b, h);
}

// ============================================================================
__device__ __forceinline__ void ssd_chunk_body(
    int blk, int tid, float* sm,
    const float* __restrict__ X, const float* __restrict__ A,
    const float* __restrict__ Bm, const float* __restrict__ Cm)
{
    float* sB = sm;
    float* sG = sm + 64 * 65;
    float* sX = sm + 2 * 64 * 65;
    float* s_cum = sX + 4096;
    float* s_eA  = s_cum + 64;
    float* s_ieA = s_eA + 64;
    const int h = blk & 15, cc = (blk >> 4) & 31, b = blk >> 9;

    const size_t gbase = ((size_t)(b * 2048 + cc * 64) * 16 + h) * 64;
#pragma unroll
    for (int u = 0; u < 4; ++u) {
        int idx4 = u * 256 + tid;
        int l = idx4 >> 4, n4 = (idx4 & 15) * 4;
        size_t go = gbase + (size_t)l * 1024 + n4;
        float4 bv = *(const float4*)(Bm + go);
        float4 cv = *(const float4*)(Cm + go);
        float4 xv = *(const float4*)(X + go);
        float* pb = sB + l * 65 + n4;
        pb[0] = bv.x; pb[1] = bv.y; pb[2] = bv.z; pb[3] = bv.w;
        float* pc = sG + l * 65 + n4;
        pc[0] = cv.x; pc[1] = cv.y; pc[2] = cv.z; pc[3] = cv.w;
        *(float4*)(sX + l * 64 + n4) = xv;
    }
    if (tid < 64) {
        float x = A[(size_t)(b * 2048 + cc * 64 + tid) * 16 + h];
#pragma unroll
        for (int o = 1; o < 32; o <<= 1) {
            float t = __shfl_up_sync(0xffffffffu, x, o);
            if ((tid & 31) >= o) x += t;
        }
        s_cum[tid] = x;
    }
    __syncthreads();
    if (tid < 64) {
        float x = s_cum[tid] + ((tid >= 32) ? s_cum[31] : 0.f);
        float e = expf(x);
        s_eA[tid] = e;
        s_ieA[tid] = expf(-x);
        g_eA[(size_t)blk * 64 + tid] = e;
        if (tid == 63) g_expsA[(b * 16 + h) * 32 + cc] = e;
    }
    __syncthreads();

    const int tl = tid >> 4, ts = tid & 15;
    const int r0 = tl * 4, c0 = ts * 4;
    float g[4][4];
#pragma unroll
    for (int ii = 0; ii < 4; ++ii)
#pragma unroll
        for (int jj = 0; jj < 4; ++jj) g[ii][jj] = 0.f;
    for (int n = 0; n < 64; ++n) {
        float cl[4], bsv[4];
#pragma unroll
        for (int ii = 0; ii < 4; ++ii) cl[ii] = sG[(r0 + ii) * 65 + n];
#pragma unroll
        for (int jj = 0; jj < 4; ++jj) bsv[jj] = sB[(c0 + jj) * 65 + n];
#pragma unroll
        for (int ii = 0; ii < 4; ++ii)
#pragma unroll
            for (int jj = 0; jj < 4; ++jj) g[ii][jj] = fmaf(cl[ii], bsv[jj], g[ii][jj]);
    }
    __syncthreads();
#pragma unroll
    for (int ii = 0; ii < 4; ++ii) {
        int l = r0 + ii;
        float el = s_eA[l];
#pragma unroll
        for (int jj = 0; jj < 4; ++jj) {
            int s = c0 + jj;
            sG[l * 65 + s] = (s <= l) ? g[ii][jj] * el * s_ieA[s] : 0.f;
        }
    }
    __syncthreads();

    float y[4][4];
#pragma unroll
    for (int ii = 0; ii < 4; ++ii)
#pragma unroll
        for (int jj = 0; jj < 4; ++jj) y[ii][jj] = 0.f;
    for (int s = 0; s < 64; ++s) {
        float4 xv = *(const float4*)(sX + s * 64 + c0);
        float gl[4];
#pragma unroll
        for (int ii = 0; ii < 4; ++ii) gl[ii] = sG[(r0 + ii) * 65 + s];
#pragma unroll
        for (int ii = 0; ii < 4; ++ii) {
            y[ii][0] = fmaf(gl[ii], xv.x, y[ii][0]);
            y[ii][1] = fmaf(gl[ii], xv.y, y[ii][1]);
            y[ii][2] = fmaf(gl[ii], xv.z, y[ii][2]);
            y[ii][3] = fmaf(gl[ii], xv.w, y[ii][3]);
        }
    }
#pragma unroll
    for (int ii = 0; ii < 4; ++ii) {
        int l = r0 + ii;
        *(float4*)(g_yd + (size_t)(b * 2048 + cc * 64 + l) * 1024 + h * 64 + c0) =
            make_float4(y[ii][0], y[ii][1], y[ii][2], y[ii][3]);
    }

    float stt[4][4];
#pragma unroll
    for (int ii = 0; ii < 4; ++ii)
#pragma unroll
        for (int jj = 0; jj < 4; ++jj) stt[ii][jj] = 0.f;
    const float eA63 = s_eA[63];
    for (int l = 0; l < 64; ++l) {
        float ds = eA63 * s_ieA[l];
        float4 xv = *(const float4*)(sX + l * 64 + r0);
        float xw[4] = { xv.x * ds, xv.y * ds, xv.z * ds, xv.w * ds };
        float bv[4];
#pragma unroll
        for (int jj = 0; jj < 4; ++jj) bv[jj] = sB[l * 65 + c0 + jj];
#pragma unroll
        for (int ii = 0; ii < 4; ++ii)
#pragma unroll
            for (int jj = 0; jj < 4; ++jj) stt[ii][jj] = fmaf(xw[ii], bv[jj], stt[ii][jj]);
    }
#pragma unroll
    for (int ii = 0; ii < 4; ++ii)
        *(float4*)(g_states + (size_t)blk * 4096 + (size_t)(r0 + ii) * 64 + c0) =
            make_float4(stt[ii][0], stt[ii][1], stt[ii][2], stt[ii][3]);
}

// off tile: g_yd[tile] += eA[l] * (C . R^T)
__device__ __forceinline__ void ssd_off_tile(
    int blk, int tid, float* sm, const float* __restrict__ Cm)
{
    float* sC  = sm;
    float* sR  = sm + 64 * 65;
    float* s_e = sm + 2 * 64 * 65;
    const int h = blk & 15, cc = (blk >> 4) & 31, b = blk >> 9;

    const size_t gbase = ((size_t)(b * 2048 + cc * 64) * 16 + h) * 64;
#pragma unroll
    for (int u = 0; u < 4; ++u) {
        int idx4 = u * 256 + tid;
        int l = idx4 >> 4, n4 = (idx4 & 15) * 4;
        float4 cv = *(const float4*)(Cm + gbase + (size_t)l * 1024 + n4);
        float4 rv = *(const float4*)(g_R + (size_t)blk * 4096 + (size_t)idx4 * 4);
        float* pc = sC + l * 65 + n4;
        pc[0] = cv.x; pc[1] = cv.y; pc[2] = cv.z; pc[3] = cv.w;
        float* pr = sR + l * 65 + n4;
        pr[0] = rv.x; pr[1] = rv.y; pr[2] = rv.z; pr[3] = rv.w;
    }
    if (tid < 64) s_e[tid] = g_eA[(size_t)blk * 64 + tid];
    __syncthreads();

    const int tl = tid >> 4, ts = tid & 15;
    const int l0 = tl * 4, p0 = ts * 4;
    float acc[4][4];
#pragma unroll
    for (int ii = 0; ii < 4; ++ii)
#pragma unroll
        for (int jj = 0; jj < 4; ++jj) acc[ii][jj] = 0.f;
    for (int n = 0; n < 64; ++n) {
        float cl[4], rv[4];
#pragma unroll
        for (int ii = 0; ii < 4; ++ii) cl[ii] = sC[(l0 + ii) * 65 + n];
#pragma unroll
        for (int jj = 0; jj < 4; ++jj) rv[jj] = sR[(p0 + jj) * 65 + n];
#pragma unroll
        for (int ii = 0; ii < 4; ++ii)
#pragma unroll
            for (int jj = 0; jj < 4; ++jj) acc[ii][jj] = fmaf(cl[ii], rv[jj], acc[ii][jj]);
    }
#pragma unroll
    for (int ii = 0; ii < 4; ++ii) {
        int l = l0 + ii;
        float e = s_e[l];
        size_t ofs = (size_t)(b * 2048 + cc * 64 + l) * 1024 + h * 64 + p0;
        float4* po = (float4*)(g_yd + ofs);
        float4 o = *po;
        o.x += e * acc[ii][0];
        o.y += e * acc[ii][1];
        o.z += e * acc[ii][2];
        o.w += e * acc[ii][3];
        *po = o;
    }
    __syncthreads();
}

// ============================================================================
__global__ void __launch_bounds__(256, 1) fused_kernel(
    const float* __restrict__ X, const float* __restrict__ A,
    const float* __restrict__ Bm, const float* __restrict__ Cm,
    const float* __restrict__ rr, const float* __restrict__ kk,
    const float* __restrict__ vv, const float* __restrict__ ww,
    const float* __restrict__ bo, float* __restrict__ out)
{
    extern __shared__ float sm[];
    const int tid = threadIdx.x;
    if (blockIdx.x < 32) {
        wkv_block(blockIdx.x, tid, sm, rr, kk, vv, ww, bo, out);
        return;
    }
    const int blk = blockIdx.x - 32;
    ssd_chunk_body(blk, tid, sm, X, A, Bm, Cm);
    __threadfence();
    __syncthreads();
    if (tid == 0) atomicAdd(&g_cnt1, 1u);
    if (blk >= 64) return;

    if (tid == 0) { while (atomicAdd(&g_cnt1, 0u) < 1024u) __nanosleep(256); }
    __syncthreads();
    __threadfence();

    {
        const int bh = blk >> 1;
        const int b = bh >> 4, h = bh & 15;
        const int e0 = (blk & 1) * 2048 + tid * 8;
        const float* es = g_expsA + bh * 32;
        float4 R0 = make_float4(0.f, 0.f, 0.f, 0.f);
        float4 R1 = make_float4(0.f, 0.f, 0.f, 0.f);
#pragma unroll 1
        for (int c = 0; c < 32; ++c) {
            size_t idx = (size_t)(b * 512 + c * 16 + h) * 4096 + e0;
            *(float4*)(g_R + idx)     = R0;
            *(float4*)(g_R + idx + 4) = R1;
            const float s = es[c];
            float4 s0 = *(const float4*)(g_states + idx);
            float4 s1 = *(const float4*)(g_states + idx + 4);
            R0.x = fmaf(R0.x, s, s0.x); R0.y = fmaf(R0.y, s, s0.y);
            R0.z = fmaf(R0.z, s, s0.z); R0.w = fmaf(R0.w, s, s0.w);
            R1.x = fmaf(R1.x, s, s1.x); R1.y = fmaf(R1.y, s, s1.y);
            R1.z = fmaf(R1.z, s, s1.z); R1.w = fmaf(R1.w, s, s1.w);
        }
    }
    __threadfence();
    __syncthreads();
    if (tid == 0) {
        atomicAdd(&g_cnt2, 1u);
        while (atomicAdd(&g_cnt2, 0u) < 64u) __nanosleep(256);
    }
    __syncthreads();
    __threadfence();

#pragma unroll 1
    for (int t = 0; t < 16; ++t)
        ssd_off_tile(blk * 16 + t, tid, sm, Cm);
}

__global__ void __launch_bounds__(256) add_kernel(float* __restrict__ out)
{
    const size_t i = (size_t)blockIdx.x * 256 + threadIdx.x;
    float4 o = ((float4*)out)[i];
    float4 yd = ((const float4*)g_yd)[i];
    o.x += yd.x; o.y += yd.y; o.z += yd.z; o.w += yd.w;
    ((float4*)out)[i] = o;
    if (blockIdx.x == 0 && threadIdx.x == 0) { g_cnt1 = 0u; g_cnt2 = 0u; }
}

extern "C" void kernel_launch(void* const* d_in, const int* in_sizes, int n_in,
                              void* d_out, int out_size)
{
    (void)in_sizes; (void)n_in; (void)out_size;
    const float* X  = (const float*)d_in[0];
    const float* A  = (const float*)d_in[1];
    const float* B  = (const float*)d_in[2];
    const float* C  = (const float*)d_in[3];
    const float* r  = (const float*)d_in[4];
    const float* k  = (const float*)d_in[5];
    const float* v  = (const float*)d_in[6];
    const float* w  = (const float*)d_in[7];
    const float* bo = (const float*)d_in[8];
    float* out = (float*)d_out;

    const int FUSED_SMEM = WKV_SMEM_FLOATS * 4;   // 107072 B
    cudaFuncSetAttribute(fused_kernel,
                         cudaFuncAttributeMaxDynamicSharedMemorySize, FUSED_SMEM);

    fused_kernel<<<1056, 256, FUSED_SMEM>>>(X, A, B, C, r, k, v, w, bo, out);
    add_kernel<<<(2 * 2048 * 1024) / (4 * 256), 256>>>(out);
}

// round 15
// speedup vs baseline: 1.3118x; 1.3118x over previous
#include <cuda_runtime.h>
#include <cstdint>
#include <cstddef>
typedef unsigned long long ull;

__device__ float g_states[2*32*16*64*64];
__device__ float g_R[2*32*16*64*64];
__device__ float g_eA[1024*64];
__device__ float g_expsA[32*32];
__device__ float g_yd[2*2048*1024];     // Y_diag, then += e*C.R^T (SSD total)
__device__ unsigned g_cnt1;             // chunk-done counter (reset by add kernel)
__device__ unsigned g_cnt2;             // scan-done counter

__device__ __forceinline__ void cp_async16(float* dst, const float* src) {
    unsigned s = (unsigned)__cvta_generic_to_shared(dst);
    asm volatile("cp.async.cg.shared.global [%0], [%1], 16;\n" :: "r"(s), "l"(src));
}
__device__ __forceinline__ void cp_commit() { asm volatile("cp.async.commit_group;\n"); }
__device__ __forceinline__ void cp_wait1()  { asm volatile("cp.async.wait_group 1;\n" ::: "memory"); }
__device__ __forceinline__ void cp_wait0()  { asm volatile("cp.async.wait_group 0;\n" ::: "memory"); }
__device__ __forceinline__ ull f2fma(ull a, ull b, ull c) {
    ull d; asm("fma.rn.f32x2 %0, %1, %2, %3;" : "=l"(d) : "l"(a), "l"(b), "l"(c)); return d;
}
__device__ __forceinline__ ull f2mul(ull a, ull b) {
    ull d; asm("mul.rn.f32x2 %0, %1, %2;" : "=l"(d) : "l"(a), "l"(b)); return d;
}
__device__ __forceinline__ ull f2add(ull a, ull b) {
    ull d; asm("add.rn.f32x2 %0, %1, %2;" : "=l"(d) : "l"(a), "l"(b)); return d;
}
__device__ __forceinline__ ull pk2(float lo, float hi) {
    ull r; asm("mov.b64 %0, {%1, %2};" : "=l"(r) : "f"(lo), "f"(hi)); return r;
}
__device__ __forceinline__ float2 upk2(ull p) {
    float2 f; asm("mov.b64 {%0, %1}, %2;" : "=f"(f.x), "=f"(f.y) : "l"(p)); return f;
}
__device__ __forceinline__ int swz_chunk(int c) { return ((c & 7) << 1) | (c >> 3); }
__device__ __forceinline__ int swz_pos(int j)   { return (swz_chunk(j >> 2) << 2) | (j & 3); }

#define BAR_ALL()  asm volatile("bar.sync 1, 256;" ::: "memory")
#define BAR_PROD() asm volatile("bar.sync 2, 128;" ::: "memory")
#define BAR_HELP() asm volatile("bar.sync 3, 128;" ::: "memory")

#define OFF_DL 20480
#define OFF_DK 22528
#define OFF_NW 22544
#define OFF_C2 24592
#define OFF_WT 26640
#define WKV_SMEM_FLOATS 26768

__device__ __forceinline__ void wkv_precompute(int wn, int tid, float* sm)
{
    if (tid >= 64) return;
    const int j = tid, pj = swz_pos(j);
    const float* pr = sm + (wn & 3) * 5120;
    float* nw = sm + OFF_NW + (wn & 1) * 1024;
    float* c2 = sm + OFF_C2 + (wn & 1) * 1024;
    float W = 1.f;
#pragma unroll
    for (int t = 0; t < 16; ++t) {
        nw[t * 64 + j] = -W;
        W *= pr[3072 + t * 64 + j];
        c2[t * 64 + j] = __fdividef(pr[4096 + t * 64 + j] * pr[1024 + t * 64 + pj], W);
    }
    sm[OFF_WT + (wn & 1) * 64 + j] = W;
}

__device__ __forceinline__ void wkv_producer(int tid, float* sm)
{
    const int i = tid >> 1, h2 = tid & 1;
    const int pos_i = swz_pos(i);
    ull S2[16];
#pragma unroll
    for (int u = 0; u < 16; ++u) S2[u] = 0ull;

#pragma unroll 1
    for (int win = 0; win < 128; ++win) {
        const float* pr = sm + (win & 3) * 5120;
        float* dl = sm + OFF_DL + (win & 1) * 1024;
        const float* nw = sm + OFF_NW + (win & 1) * 1024;
        const float* c2 = sm + OFF_C2 + (win & 1) * 1024;

#pragma unroll 1
        for (int s = 0; s < 8; ++s) {
            const int st0 = 2 * s, st1 = st0 + 1;
            const float* k0s = pr + 1024 + st0 * 64;
            const float* k1s = pr + 1024 + st1 * 64;
            ull ka[16], kb[16];
#pragma unroll
            for (int u = 0; u < 8; ++u) {
                float4 qa = *(const float4*)(k0s + (2 * u + h2) * 4);
                float4 qb = *(const float4*)(k1s + (2 * u + h2) * 4);
                ka[2*u] = *(ull*)&qa.x; ka[2*u+1] = *(ull*)&qa.z;
                kb[2*u] = *(ull*)&qb.x; kb[2*u+1] = *(ull*)&qb.z;
            }
            ull a0 = f2mul(S2[0], ka[0]);
            ull a1 = f2mul(S2[1], ka[1]);
            ull a2 = f2mul(S2[2], ka[2]);
            ull a3 = f2mul(S2[3], ka[3]);
            ull e0 = f2mul(S2[0], kb[0]);
            ull e1 = f2mul(S2[1], kb[1]);
            ull e2 = f2mul(S2[2], kb[2]);
            ull e3 = f2mul(S2[3], kb[3]);
#pragma unroll
            for (int u = 1; u < 4; ++u) {
                a0 = f2fma(S2[4*u+0], ka[4*u+0], a0);
                a1 = f2fma(S2[4*u+1], ka[4*u+1], a1);
                a2 = f2fma(S2[4*u+2], ka[4*u+2], a2);
                a3 = f2fma(S2[4*u+3], ka[4*u+3], a3);
                e0 = f2fma(S2[4*u+0], kb[4*u+0], e0);
                e1 = f2fma(S2[4*u+1], kb[4*u+1], e1);
                e2 = f2fma(S2[4*u+2], kb[4*u+2], e2);
                e3 = f2fma(S2[4*u+3], kb[4*u+3], e3);
            }
            a0 = f2add(a0, a1); a2 = f2add(a2, a3); a0 = f2add(a0, a2);
            e0 = f2add(e0, e1); e2 = f2add(e2, e3); e0 = f2add(e0, e2);
            float2 af = upk2(a0), ef = upk2(e0);
            float accA = af.x + af.y;
            float accB = ef.x + ef.y;
            accA += __shfl_xor_sync(0xffffffffu, accA, 1);
            accB += __shfl_xor_sync(0xffffffffu, accB, 1);

            const float v0  = pr[2048 + st0*64 + i];
            const float nW0 = nw[st0*64 + i];
            const float c0  = c2[st0*64 + i];
            const float v1  = pr[2048 + st1*64 + i];
            const float nW1 = nw[st1*64 + i];
            const float c1  = c2[st1*64 + i];

            dl[st0*64 + pos_i] = fmaf(nW0, accA, v0);
            const ull c02 = pk2(c0, c0);
            BAR_PROD();

            ull u0 = 0ull, u1 = 0ull, u2 = 0ull, u3 = 0ull;
            {
                float4 dq0 = *(const float4*)(dl + st0*64 + (0 + h2)*4);
                float4 dq1 = *(const float4*)(dl + st0*64 + (2 + h2)*4);
                float4 dq2 = *(const float4*)(dl + st0*64 + (4 + h2)*4);
                float4 dq3 = *(const float4*)(dl + st0*64 + (6 + h2)*4);
                float4 dq4 = *(const float4*)(dl + st0*64 + (8 + h2)*4);
                float4 dq5 = *(const float4*)(dl + st0*64 + (10 + h2)*4);
                float4 dq6 = *(const float4*)(dl + st0*64 + (12 + h2)*4);
                float4 dq7 = *(const float4*)(dl + st0*64 + (14 + h2)*4);
                ull t0, t1;
#define UPD(Q, bu, ux, uy) \
                t0 = *(ull*)&Q.x; t1 = *(ull*)&Q.z; \
                ux = f2fma(t0, kb[2*(bu)],   ux); \
                uy = f2fma(t1, kb[2*(bu)+1], uy); \
                S2[2*(bu)]   = f2fma(c02, t0, S2[2*(bu)]); \
                S2[2*(bu)+1] = f2fma(c02, t1, S2[2*(bu)+1]);
                UPD(dq0, 0, u0, u1) UPD(dq1, 1, u2, u3)
                UPD(dq2, 2, u0, u1) UPD(dq3, 3, u2, u3)
                UPD(dq4, 4, u0, u1) UPD(dq5, 5, u2, u3)
                UPD(dq6, 6, u0, u1) UPD(dq7, 7, u2, u3)
#undef UPD
            }
            u0 = f2add(u0, u1); u2 = f2add(u2, u3); u0 = f2add(u0, u2);
            float2 uf = upk2(u0);
            float uu = uf.x + uf.y;
            uu += __shfl_xor_sync(0xffffffffu, uu, 1);

            dl[st1*64 + pos_i] = fmaf(nW1, fmaf(c0, uu, accB), v1);
            const ull c12 = pk2(c1, c1);
            BAR_PROD();

#pragma unroll
            for (int u = 0; u < 8; ++u) {
                float4 dq = *(const float4*)(dl + st1*64 + (2*u + h2)*4);
                S2[2*u]   = f2fma(c12, *(ull*)&dq.x, S2[2*u]);
                S2[2*u+1] = f2fma(c12, *(ull*)&dq.z, S2[2*u+1]);
            }
        }
        const float wti = sm[OFF_WT + (win & 1) * 64 + i];
        const ull w2 = pk2(wti, wti);
#pragma unroll
        for (int u = 0; u < 16; ++u) S2[u] = f2mul(S2[u], w2);
        BAR_ALL();
    }
}

__device__ __forceinline__ void wkv_emit_window(
    int wn, int tid, float* sm, float* __restrict__ out, int b, int h)
{
    const float* pr = sm + (wn & 3) * 5120;
    const float* dl = sm + OFF_DL + (wn & 1) * 1024;
    float* s_dk = sm + OFF_DK;
    const int lane = tid & 31, wid = tid >> 5;
#pragma unroll
    for (int rep = 0; rep < 4; ++rep) {
        const int st = rep * 4 + wid;
        const int pp = swz_chunk(lane >> 1) * 4 + (lane & 1) * 2;
        float2 kv  = *(const float2*)(pr + 1024 + st * 64 + pp);
        float2 dl2 = *(const float2*)(dl + st * 64 + pp);
        float pd = fmaf(dl2.x, kv.x, dl2.y * kv.y);
#pragma unroll
        for (int off = 16; off > 0; off >>= 1)
            pd += __shfl_xor_sync(0xffffffffu, pd, off);
        if (lane == 0) s_dk[st] = pd;
    }
    BAR_HELP();
#pragma unroll
    for (int rep = 0; rep < 4; ++rep) {
        const int idx = rep * 128 + tid;
        const int st = idx >> 5, cp2 = idx & 31;
        const int col = cp2 * 2;
        const int pp = swz_chunk(cp2 >> 1) * 4 + (cp2 & 1) * 2;
        float2 dv = *(const float2*)(dl + st * 64 + pp);
        float2 k_ = *(const float2*)(pr + 1024 + st * 64 + pp);
        float2 r_ = *(const float2*)(pr + st * 64 + col);
        float2 v_ = *(const float2*)(pr + 2048 + st * 64 + col);
        float2 w_ = *(const float2*)(pr + 3072 + st * 64 + col);
        float2 b_ = *(const float2*)(pr + 4096 + st * 64 + col);
        const float dk = s_dk[st];
        float2 y;
        y.x = r_.x * fmaf(b_.x * k_.x, dk, w_.x * (v_.x - dv.x));
        y.y = r_.y * fmaf(b_.y * k_.y, dk, w_.y * (v_.y - dv.y));
        *(float2*)(out + (size_t)(b * 2048 + wn * 16 + st) * 1024 + h * 64 + col) = y;
    }
}

__device__ __forceinline__ void wkv_helper(
    int tid, float* sm, const float* const* arrs, size_t base,
    float* __restrict__ out, int b, int h)
{
#pragma unroll 1
    for (int win = 0; win < 128; ++win) {
        if (win + 2 < 128) {
            const int dst = ((win + 2) & 3) * 5120;
#pragma unroll
            for (int a = 0; a < 5; ++a)
#pragma unroll
                for (int rep = 0; rep < 2; ++rep) {
                    int x = rep * 128 + tid;
                    int st = x >> 4, c = x & 15;
                    int dc = (a == 1) ? swz_chunk(c) : c;
                    cp_async16(&sm[dst + a * 1024 + st * 64 + dc * 4],
                               arrs[a] + base + (size_t)((win + 2) * 16 + st) * 64 + c * 4);
                }
            cp_commit();
        }
        if (win >= 1) wkv_emit_window(win - 1, tid, sm, out, b, h);
        if (win >= 126) cp_wait0(); else cp_wait1();
        BAR_HELP();   // fence all helpers' retired cp.async before cross-reads
        if (win + 1 < 128) wkv_precompute(win + 1, tid, sm);
        BAR_ALL();
    }
    wkv_emit_window(127, tid, sm, out, b, h);
}

__device__ __forceinline__ void wkv_block(
    int bh, int tid, float* sm,
    const float* __restrict__ rr, const float* __restrict__ kk_g,
    const float* __restrict__ vv_g, const float* __restrict__ ww_g,
    const float* __restrict__ bo_g, float* __restrict__ out)
{
    const int b = bh >> 4, h = bh & 15;
    const size_t base = (size_t)bh * 2048 * 64;
    const float* arrs[5] = { rr, kk_g, vv_g, ww_g, bo_g };
#pragma unroll
    for (int wv = 0; wv < 2; ++wv)
#pragma unroll
        for (int a = 0; a < 5; ++a) {
            int st = tid >> 4, c = tid & 15;
            int dc = (a == 1) ? swz_chunk(c) : c;
            cp_async16(&sm[wv * 5120 + a * 1024 + st * 64 + dc * 4],
                       arrs[a] + base + (size_t)(wv * 16 + st) * 64 + c * 4);
        }
    cp_commit();
    cp_wait0();
    BAR_ALL();
    if (tid >= 128) wkv_precompute(0, tid - 128, sm);
    BAR_ALL();
    if (tid < 128) wkv_producer(tid, sm);
    else           wkv_helper(tid - 128, sm, arrs, base, out, b, h);
}

// ============================================================================
__device__ __forceinline__ void ssd_chunk_body(
    int blk, int tid, float* sm,
    const float* __restrict__ X, const float* __restrict__ A,
    const float* __restrict__ Bm, const float* __restrict__ Cm)
{
    float* sB = sm;
    float* sG = sm + 64 * 65;
    float* sX = sm + 2 * 64 * 65;
    float* s_cum = sX + 4096;
    float* s_eA  = s_cum + 64;
    float* s_ieA = s_eA + 64;
    const int h = blk & 15, cc = (blk >> 4) & 31, b = blk >> 9;

    const size_t gbase = ((size_t)(b * 2048 + cc * 64) * 16 + h) * 64;
#pragma unroll
    for (int u = 0; u < 4; ++u) {
        int idx4 = u * 256 + tid;
        int l = idx4 >> 4, n4 = (idx4 & 15) * 4;
        size_t go = gbase + (size_t)l * 1024 + n4;
        float4 bv = *(const float4*)(Bm + go);
        float4 cv = *(const float4*)(Cm + go);
        float4 xv = *(const float4*)(X + go);
        float* pb = sB + l * 65 + n4;
        pb[0] = bv.x; pb[1] = bv.y; pb[2] = bv.z; pb[3] = bv.w;
        float* pc = sG + l * 65 + n4;
        pc[0] = cv.x; pc[1] = cv.y; pc[2] = cv.z; pc[3] = cv.w;
        *(float4*)(sX + l * 64 + n4) = xv;
    }
    if (tid < 64) {
        float x = A[(size_t)(b * 2048 + cc * 64 + tid) * 16 + h];
#pragma unroll
        for (int o = 1; o < 32; o <<= 1) {
            float t = __shfl_up_sync(0xffffffffu, x, o);
            if ((tid & 31) >= o) x += t;
        }
        s_cum[tid] = x;
    }
    __syncthreads();
    if (tid < 64) {
        float x = s_cum[tid] + ((tid >= 32) ? s_cum[31] : 0.f);
        float e = expf(x);
        s_eA[tid] = e;
        s_ieA[tid] = expf(-x);
        g_eA[(size_t)blk * 64 + tid] = e;
        if (tid == 63) g_expsA[(b * 16 + h) * 32 + cc] = e;
    }
    __syncthreads();

    const int tl = tid >> 4, ts = tid & 15;
    const int r0 = tl * 4, c0 = ts * 4;
    float g[4][4];
#pragma unroll
    for (int ii = 0; ii < 4; ++ii)
#pragma unroll
        for (int jj = 0; jj < 4; ++jj) g[ii][jj] = 0.f;
    for (int n = 0; n < 64; ++n) {
        float cl[4], bsv[4];
#pragma unroll
        for (int ii = 0; ii < 4; ++ii) cl[ii] = sG[(r0 + ii) * 65 + n];
#pragma unroll
        for (int jj = 0; jj < 4; ++jj) bsv[jj] = sB[(c0 + jj) * 65 + n];
#pragma unroll
        for (int ii = 0; ii < 4; ++ii)
#pragma unroll
            for (int jj = 0; jj < 4; ++jj) g[ii][jj] = fmaf(cl[ii], bsv[jj], g[ii][jj]);
    }
    __syncthreads();
#pragma unroll
    for (int ii = 0; ii < 4; ++ii) {
        int l = r0 + ii;
        float el = s_eA[l];
#pragma unroll
        for (int jj = 0; jj < 4; ++jj) {
            int s = c0 + jj;
            sG[l * 65 + s] = (s <= l) ? g[ii][jj] * el * s_ieA[s] : 0.f;
        }
    }
    __syncthreads();

    float y[4][4];
#pragma unroll
    for (int ii = 0; ii < 4; ++ii)
#pragma unroll
        for (int jj = 0; jj < 4; ++jj) y[ii][jj] = 0.f;
    for (int s = 0; s < 64; ++s) {
        float4 xv = *(const float4*)(sX + s * 64 + c0);
        float gl[4];
#pragma unroll
        for (int ii = 0; ii < 4; ++ii) gl[ii] = sG[(r0 + ii) * 65 + s];
#pragma unroll
        for (int ii = 0; ii < 4; ++ii) {
            y[ii][0] = fmaf(gl[ii], xv.x, y[ii][0]);
            y[ii][1] = fmaf(gl[ii], xv.y, y[ii][1]);
            y[ii][2] = fmaf(gl[ii], xv.z, y[ii][2]);
            y[ii][3] = fmaf(gl[ii], xv.w, y[ii][3]);
        }
    }
#pragma unroll
    for (int ii = 0; ii < 4; ++ii) {
        int l = r0 + ii;
        *(float4*)(g_yd + (size_t)(b * 2048 + cc * 64 + l) * 1024 + h * 64 + c0) =
            make_float4(y[ii][0], y[ii][1], y[ii][2], y[ii][3]);
    }

    float stt[4][4];
#pragma unroll
    for (int ii = 0; ii < 4; ++ii)
#pragma unroll
        for (int jj = 0; jj < 4; ++jj) stt[ii][jj] = 0.f;
    const float eA63 = s_eA[63];
    for (int l = 0; l < 64; ++l) {
        float ds = eA63 * s_ieA[l];
        float4 xv = *(const float4*)(sX + l * 64 + r0);
        float xw[4] = { xv.x * ds, xv.y * ds, xv.z * ds, xv.w * ds };
        float bv[4];
#pragma unroll
        for (int jj = 0; jj < 4; ++jj) bv[jj] = sB[l * 65 + c0 + jj];
#pragma unroll
        for (int ii = 0; ii < 4; ++ii)
#pragma unroll
            for (int jj = 0; jj < 4; ++jj) stt[ii][jj] = fmaf(xw[ii], bv[jj], stt[ii][jj]);
    }
#pragma unroll
    for (int ii = 0; ii < 4; ++ii)
        *(float4*)(g_states + (size_t)blk * 4096 + (size_t)(r0 + ii) * 64 + c0) =
            make_float4(stt[ii][0], stt[ii][1], stt[ii][2], stt[ii][3]);
}

// off tile: g_yd[tile] += eA[l] * (C . R^T)
__device__ __forceinline__ void ssd_off_tile(
    int blk, int tid, float* sm, const float* __restrict__ Cm)
{
    float* sC  = sm;
    float* sR  = sm + 64 * 65;
    float* s_e = sm + 2 * 64 * 65;
    const int h = blk & 15, cc = (blk >> 4) & 31, b = blk >> 9;

    const size_t gbase = ((size_t)(b * 2048 + cc * 64) * 16 + h) * 64;
#pragma unroll
    for (int u = 0; u < 4; ++u) {
        int idx4 = u * 256 + tid;
        int l = idx4 >> 4, n4 = (idx4 & 15) * 4;
        float4 cv = *(const float4*)(Cm + gbase + (size_t)l * 1024 + n4);
        float4 rv = *(const float4*)(g_R + (size_t)blk * 4096 + (size_t)idx4 * 4);
        float* pc = sC + l * 65 + n4;
        pc[0] = cv.x; pc[1] = cv.y; pc[2] = cv.z; pc[3] = cv.w;
        float* pr = sR + l * 65 + n4;
        pr[0] = rv.x; pr[1] = rv.y; pr[2] = rv.z; pr[3] = rv.w;
    }
    if (tid < 64) s_e[tid] = g_eA[(size_t)blk * 64 + tid];
    __syncthreads();

    const int tl = tid >> 4, ts = tid & 15;
    const int l0 = tl * 4, p0 = ts * 4;
    float acc[4][4];
#pragma unroll
    for (int ii = 0; ii < 4; ++ii)
#pragma unroll
        for (int jj = 0; jj < 4; ++jj) acc[ii][jj] = 0.f;
    for (int n = 0; n < 64; ++n) {
        float cl[4], rv[4];
#pragma unroll
        for (int ii = 0; ii < 4; ++ii) cl[ii] = sC[(l0 + ii) * 65 + n];
#pragma unroll
        for (int jj = 0; jj < 4; ++jj) rv[jj] = sR[(p0 + jj) * 65 + n];
#pragma unroll
        for (int ii = 0; ii < 4; ++ii)
#pragma unroll
            for (int jj = 0; jj < 4; ++jj) acc[ii][jj] = fmaf(cl[ii], rv[jj], acc[ii][jj]);
    }
#pragma unroll
    for (int ii = 0; ii < 4; ++ii) {
        int l = l0 + ii;
        float e = s_e[l];
        size_t ofs = (size_t)(b * 2048 + cc * 64 + l) * 1024 + h * 64 + p0;
        float4* po = (float4*)(g_yd + ofs);
        float4 o = *po;
        o.x += e * acc[ii][0];
        o.y += e * acc[ii][1];
        o.z += e * acc[ii][2];
        o.w += e * acc[ii][3];
        *po = o;
    }
    __syncthreads();
}

// ============================================================================
__global__ void __launch_bounds__(256, 1) fused_kernel(
    const float* __restrict__ X, const float* __restrict__ A,
    const float* __restrict__ Bm, const float* __restrict__ Cm,
    const float* __restrict__ rr, const float* __restrict__ kk,
    const float* __restrict__ vv, const float* __restrict__ ww,
    const float* __restrict__ bo, float* __restrict__ out)
{
    extern __shared__ float sm[];
    const int tid = threadIdx.x;
    if (blockIdx.x < 32) {
        wkv_block(blockIdx.x, tid, sm, rr, kk, vv, ww, bo, out);
        return;
    }
    const int blk = blockIdx.x - 32;
    ssd_chunk_body(blk, tid, sm, X, A, Bm, Cm);
    __threadfence();
    __syncthreads();
    if (tid == 0) atomicAdd(&g_cnt1, 1u);
    if (blk >= 64) return;

    if (tid == 0) { while (atomicAdd(&g_cnt1, 0u) < 1024u) __nanosleep(256); }
    __syncthreads();
    __threadfence();

    {
        const int bh = blk >> 1;
        const int b = bh >> 4, h = bh & 15;
        const int e0 = (blk & 1) * 2048 + tid * 8;
        const float* es = g_expsA + bh * 32;
        float4 R0 = make_float4(0.f, 0.f, 0.f, 0.f);
        float4 R1 = make_float4(0.f, 0.f, 0.f, 0.f);
#pragma unroll 1
        for (int c = 0; c < 32; ++c) {
            size_t idx = (size_t)(b * 512 + c * 16 + h) * 4096 + e0;
            *(float4*)(g_R + idx)     = R0;
            *(float4*)(g_R + idx + 4) = R1;
            const float s = es[c];
            float4 s0 = *(const float4*)(g_states + idx);
            float4 s1 = *(const float4*)(g_states + idx + 4);
            R0.x = fmaf(R0.x, s, s0.x); R0.y = fmaf(R0.y, s, s0.y);
            R0.z = fmaf(R0.z, s, s0.z); R0.w = fmaf(R0.w, s, s0.w);
            R1.x = fmaf(R1.x, s, s1.x); R1.y = fmaf(R1.y, s, s1.y);
            R1.z = fmaf(R1.z, s, s1.z); R1.w = fmaf(R1.w, s, s1.w);
        }
    }
    __threadfence();
    __syncthreads();
    if (tid == 0) {
        atomicAdd(&g_cnt2, 1u);
        while (atomicAdd(&g_cnt2, 0u) < 64u) __nanosleep(256);
    }
    __syncthreads();
    __threadfence();

#pragma unroll 1
    for (int t = 0; t < 16; ++t)
        ssd_off_tile(blk * 16 + t, tid, sm, Cm);
}

__global__ void __launch_bounds__(256) add_kernel(float* __restrict__ out)
{
    const size_t i0 = (size_t)blockIdx.x * 512 + threadIdx.x;   // float4 index
#pragma unroll
    for (int r = 0; r < 2; ++r) {
        const size_t i = i0 + r * 256;
        float4 o = ((float4*)out)[i];
        float4 yd = ((const float4*)g_yd)[i];
        o.x += yd.x; o.y += yd.y; o.z += yd.z; o.w += yd.w;
        ((float4*)out)[i] = o;
    }
    if (blockIdx.x == 0 && threadIdx.x == 0) { g_cnt1 = 0u; g_cnt2 = 0u; }
}

extern "C" void kernel_launch(void* const* d_in, const int* in_sizes, int n_in,
                              void* d_out, int out_size)
{
    (void)in_sizes; (void)n_in; (void)out_size;
    const float* X  = (const float*)d_in[0];
    const float* A  = (const float*)d_in[1];
    const float* B  = (const float*)d_in[2];
    const float* C  = (const float*)d_in[3];
    const float* r  = (const float*)d_in[4];
    const float* k  = (const float*)d_in[5];
    const float* v  = (const float*)d_in[6];
    const float* w  = (const float*)d_in[7];
    const float* bo = (const float*)d_in[8];
    float* out = (float*)d_out;

    const int FUSED_SMEM = WKV_SMEM_FLOATS * 4;   // 107072 B
    cudaFuncSetAttribute(fused_kernel,
                         cudaFuncAttributeMaxDynamicSharedMemorySize, FUSED_SMEM);

    fused_kernel<<<1056, 256, FUSED_SMEM>>>(X, A, B, C, r, k, v, w, bo, out);
    add_kernel<<<(2 * 2048 * 1024) / (4 * 512), 256>>>(out);
}

// round 16
// speedup vs baseline: 1.5434x; 1.1765x over previous
#include <cuda_runtime.h>
#include <cstdint>
#include <cstddef>
typedef unsigned long long ull;

__device__ float g_states[2*32*16*64*64];
__device__ float g_R[2*32*16*64*64];
__device__ float g_eA[1024*64];
__device__ float g_expsA[32*32];
__device__ float g_yd[2*2048*1024];     // Y_diag, then += e*C.R^T (SSD total)
__device__ unsigned g_cnt1;             // chunk-done counter (reset by add kernel)
__device__ unsigned g_cnt2;             // scan-done counter

__device__ __forceinline__ void cp_async16(float* dst, const float* src) {
    unsigned s = (unsigned)__cvta_generic_to_shared(dst);
    asm volatile("cp.async.cg.shared.global [%0], [%1], 16;\n" :: "r"(s), "l"(src));
}
__device__ __forceinline__ void cp_commit() { asm volatile("cp.async.commit_group;\n"); }
__device__ __forceinline__ void cp_wait1()  { asm volatile("cp.async.wait_group 1;\n" ::: "memory"); }
__device__ __forceinline__ void cp_wait0()  { asm volatile("cp.async.wait_group 0;\n" ::: "memory"); }
__device__ __forceinline__ ull f2fma(ull a, ull b, ull c) {
    ull d; asm("fma.rn.f32x2 %0, %1, %2, %3;" : "=l"(d) : "l"(a), "l"(b), "l"(c)); return d;
}
__device__ __forceinline__ ull f2mul(ull a, ull b) {
    ull d; asm("mul.rn.f32x2 %0, %1, %2;" : "=l"(d) : "l"(a), "l"(b)); return d;
}
__device__ __forceinline__ ull f2add(ull a, ull b) {
    ull d; asm("add.rn.f32x2 %0, %1, %2;" : "=l"(d) : "l"(a), "l"(b)); return d;
}
__device__ __forceinline__ ull pk2(float lo, float hi) {
    ull r; asm("mov.b64 %0, {%1, %2};" : "=l"(r) : "f"(lo), "f"(hi)); return r;
}
__device__ __forceinline__ float2 upk2(ull p) {
    float2 f; asm("mov.b64 {%0, %1}, %2;" : "=f"(f.x), "=f"(f.y) : "l"(p)); return f;
}
__device__ __forceinline__ int swz_chunk(int c) { return ((c & 7) << 1) | (c >> 3); }
__device__ __forceinline__ int swz_pos(int j)   { return (swz_chunk(j >> 2) << 2) | (j & 3); }

#define BAR_ALL()  asm volatile("bar.sync 1, 256;" ::: "memory")
#define BAR_PROD() asm volatile("bar.sync 2, 128;" ::: "memory")
#define BAR_HELP() asm volatile("bar.sync 3, 128;" ::: "memory")

#define OFF_DL 20480
#define OFF_DK 22528
#define OFF_NW 22544
#define OFF_C2 24592
#define OFF_WT 26640
#define WKV_SMEM_FLOATS 26768

__device__ __forceinline__ void wkv_precompute(int wn, int tid, float* sm)
{
    if (tid >= 64) return;
    const int j = tid, pj = swz_pos(j);
    const float* pr = sm + (wn & 3) * 5120;
    float* nw = sm + OFF_NW + (wn & 1) * 1024;
    float* c2 = sm + OFF_C2 + (wn & 1) * 1024;
    float W = 1.f;
#pragma unroll
    for (int t = 0; t < 16; ++t) {
        nw[t * 64 + j] = -W;
        W *= pr[3072 + t * 64 + j];
        c2[t * 64 + j] = __fdividef(pr[4096 + t * 64 + j] * pr[1024 + t * 64 + pj], W);
    }
    sm[OFF_WT + (wn & 1) * 64 + j] = W;
}

__device__ __forceinline__ void wkv_producer(int tid, float* sm)
{
    const int i = tid >> 1, h2 = tid & 1;
    const int pos_i = swz_pos(i);
    ull S2[16];
#pragma unroll
    for (int u = 0; u < 16; ++u) S2[u] = 0ull;

#pragma unroll 1
    for (int win = 0; win < 128; ++win) {
        const float* pr = sm + (win & 3) * 5120;
        float* dl = sm + OFF_DL + (win & 1) * 1024;
        const float* nw = sm + OFF_NW + (win & 1) * 1024;
        const float* c2 = sm + OFF_C2 + (win & 1) * 1024;

#pragma unroll 2
        for (int s = 0; s < 8; ++s) {
            const int st0 = 2 * s, st1 = st0 + 1;
            const float* k0s = pr + 1024 + st0 * 64;
            const float* k1s = pr + 1024 + st1 * 64;

            // scalar row operands first (independent of S2 -> issue early)
            const float v0  = pr[2048 + st0*64 + i];
            const float nW0 = nw[st0*64 + i];
            const float c0  = c2[st0*64 + i];
            const float v1  = pr[2048 + st1*64 + i];
            const float nW1 = nw[st1*64 + i];
            const float c1  = c2[st1*64 + i];

            ull ka[16], kb[16];
#pragma unroll
            for (int u = 0; u < 8; ++u) {
                float4 qa = *(const float4*)(k0s + (2 * u + h2) * 4);
                float4 qb = *(const float4*)(k1s + (2 * u + h2) * 4);
                ka[2*u] = *(ull*)&qa.x; ka[2*u+1] = *(ull*)&qa.z;
                kb[2*u] = *(ull*)&qb.x; kb[2*u+1] = *(ull*)&qb.z;
            }
            ull a0 = f2mul(S2[0], ka[0]);
            ull a1 = f2mul(S2[1], ka[1]);
            ull a2 = f2mul(S2[2], ka[2]);
            ull a3 = f2mul(S2[3], ka[3]);
            ull e0 = f2mul(S2[0], kb[0]);
            ull e1 = f2mul(S2[1], kb[1]);
            ull e2 = f2mul(S2[2], kb[2]);
            ull e3 = f2mul(S2[3], kb[3]);
#pragma unroll
            for (int u = 1; u < 4; ++u) {
                a0 = f2fma(S2[4*u+0], ka[4*u+0], a0);
                a1 = f2fma(S2[4*u+1], ka[4*u+1], a1);
                a2 = f2fma(S2[4*u+2], ka[4*u+2], a2);
                a3 = f2fma(S2[4*u+3], ka[4*u+3], a3);
                e0 = f2fma(S2[4*u+0], kb[4*u+0], e0);
                e1 = f2fma(S2[4*u+1], kb[4*u+1], e1);
                e2 = f2fma(S2[4*u+2], kb[4*u+2], e2);
                e3 = f2fma(S2[4*u+3], kb[4*u+3], e3);
            }
            a0 = f2add(a0, a1); a2 = f2add(a2, a3); a0 = f2add(a0, a2);
            e0 = f2add(e0, e1); e2 = f2add(e2, e3); e0 = f2add(e0, e2);
            float2 af = upk2(a0), ef = upk2(e0);
            float accA = af.x + af.y;
            float accB = ef.x + ef.y;
            accA += __shfl_xor_sync(0xffffffffu, accA, 1);
            accB += __shfl_xor_sync(0xffffffffu, accB, 1);

            dl[st0*64 + pos_i] = fmaf(nW0, accA, v0);
            const ull c02 = pk2(c0, c0);
            BAR_PROD();

            ull u0 = 0ull, u1 = 0ull, u2 = 0ull, u3 = 0ull;
            {
                float4 dq0 = *(const float4*)(dl + st0*64 + (0 + h2)*4);
                float4 dq1 = *(const float4*)(dl + st0*64 + (2 + h2)*4);
                float4 dq2 = *(const float4*)(dl + st0*64 + (4 + h2)*4);
                float4 dq3 = *(const float4*)(dl + st0*64 + (6 + h2)*4);
                float4 dq4 = *(const float4*)(dl + st0*64 + (8 + h2)*4);
                float4 dq5 = *(const float4*)(dl + st0*64 + (10 + h2)*4);
                float4 dq6 = *(const float4*)(dl + st0*64 + (12 + h2)*4);
                float4 dq7 = *(const float4*)(dl + st0*64 + (14 + h2)*4);
                ull t0, t1;
#define UPD(Q, bu, ux, uy) \
                t0 = *(ull*)&Q.x; t1 = *(ull*)&Q.z; \
                ux = f2fma(t0, kb[2*(bu)],   ux); \
                uy = f2fma(t1, kb[2*(bu)+1], uy); \
                S2[2*(bu)]   = f2fma(c02, t0, S2[2*(bu)]); \
                S2[2*(bu)+1] = f2fma(c02, t1, S2[2*(bu)+1]);
                UPD(dq0, 0, u0, u1) UPD(dq1, 1, u2, u3)
                UPD(dq2, 2, u0, u1) UPD(dq3, 3, u2, u3)
                UPD(dq4, 4, u0, u1) UPD(dq5, 5, u2, u3)
                UPD(dq6, 6, u0, u1) UPD(dq7, 7, u2, u3)
#undef UPD
            }
            u0 = f2add(u0, u1); u2 = f2add(u2, u3); u0 = f2add(u0, u2);
            float2 uf = upk2(u0);
            float uu = uf.x + uf.y;
            uu += __shfl_xor_sync(0xffffffffu, uu, 1);

            dl[st1*64 + pos_i] = fmaf(nW1, fmaf(c0, uu, accB), v1);
            const ull c12 = pk2(c1, c1);
            BAR_PROD();

#pragma unroll
            for (int u = 0; u < 8; ++u) {
                float4 dq = *(const float4*)(dl + st1*64 + (2*u + h2)*4);
                S2[2*u]   = f2fma(c12, *(ull*)&dq.x, S2[2*u]);
                S2[2*u+1] = f2fma(c12, *(ull*)&dq.z, S2[2*u+1]);
            }
        }
        const float wti = sm[OFF_WT + (win & 1) * 64 + i];
        const ull w2 = pk2(wti, wti);
#pragma unroll
        for (int u = 0; u < 16; ++u) S2[u] = f2mul(S2[u], w2);
        BAR_ALL();
    }
}

__device__ __forceinline__ void wkv_emit_window(
    int wn, int tid, float* sm, float* __restrict__ out, int b, int h)
{
    const float* pr = sm + (wn & 3) * 5120;
    const float* dl = sm + OFF_DL + (wn & 1) * 1024;
    float* s_dk = sm + OFF_DK;
    const int lane = tid & 31, wid = tid >> 5;
#pragma unroll
    for (int rep = 0; rep < 4; ++rep) {
        const int st = rep * 4 + wid;
        const int pp = swz_chunk(lane >> 1) * 4 + (lane & 1) * 2;
        float2 kv  = *(const float2*)(pr + 1024 + st * 64 + pp);
        float2 dl2 = *(const float2*)(dl + st * 64 + pp);
        float pd = fmaf(dl2.x, kv.x, dl2.y * kv.y);
#pragma unroll
        for (int off = 16; off > 0; off >>= 1)
            pd += __shfl_xor_sync(0xffffffffu, pd, off);
        if (lane == 0) s_dk[st] = pd;
    }
    BAR_HELP();
#pragma unroll
    for (int rep = 0; rep < 4; ++rep) {
        const int idx = rep * 128 + tid;
        const int st = idx >> 5, cp2 = idx & 31;
        const int col = cp2 * 2;
        const int pp = swz_chunk(cp2 >> 1) * 4 + (cp2 & 1) * 2;
        float2 dv = *(const float2*)(dl + st * 64 + pp);
        float2 k_ = *(const float2*)(pr + 1024 + st * 64 + pp);
        float2 r_ = *(const float2*)(pr + st * 64 + col);
        float2 v_ = *(const float2*)(pr + 2048 + st * 64 + col);
        float2 w_ = *(const float2*)(pr + 3072 + st * 64 + col);
        float2 b_ = *(const float2*)(pr + 4096 + st * 64 + col);
        const float dk = s_dk[st];
        float2 y;
        y.x = r_.x * fmaf(b_.x * k_.x, dk, w_.x * (v_.x - dv.x));
        y.y = r_.y * fmaf(b_.y * k_.y, dk, w_.y * (v_.y - dv.y));
        *(float2*)(out + (size_t)(b * 2048 + wn * 16 + st) * 1024 + h * 64 + col) = y;
    }
}

__device__ __forceinline__ void wkv_helper(
    int tid, float* sm, const float* const* arrs, size_t base,
    float* __restrict__ out, int b, int h)
{
#pragma unroll 1
    for (int win = 0; win < 128; ++win) {
        if (win + 2 < 128) {
            const int dst = ((win + 2) & 3) * 5120;
#pragma unroll
            for (int a = 0; a < 5; ++a)
#pragma unroll
                for (int rep = 0; rep < 2; ++rep) {
                    int x = rep * 128 + tid;
                    int st = x >> 4, c = x & 15;
                    int dc = (a == 1) ? swz_chunk(c) : c;
                    cp_async16(&sm[dst + a * 1024 + st * 64 + dc * 4],
                               arrs[a] + base + (size_t)((win + 2) * 16 + st) * 64 + c * 4);
                }
            cp_commit();
        }
        if (win >= 1) wkv_emit_window(win - 1, tid, sm, out, b, h);
        if (win >= 126) cp_wait0(); else cp_wait1();
        BAR_HELP();   // fence all helpers' retired cp.async before cross-reads
        if (win + 1 < 128) wkv_precompute(win + 1, tid, sm);
        BAR_ALL();
    }
    wkv_emit_window(127, tid, sm, out, b, h);
}

__device__ __forceinline__ void wkv_block(
    int bh, int tid, float* sm,
    const float* __restrict__ rr, const float* __restrict__ kk_g,
    const float* __restrict__ vv_g, const float* __restrict__ ww_g,
    const float* __restrict__ bo_g, float* __restrict__ out)
{
    const int b = bh >> 4, h = bh & 15;
    const size_t base = (size_t)bh * 2048 * 64;
    const float* arrs[5] = { rr, kk_g, vv_g, ww_g, bo_g };
#pragma unroll
    for (int wv = 0; wv < 2; ++wv)
#pragma unroll
        for (int a = 0; a < 5; ++a) {
            int st = tid >> 4, c = tid & 15;
            int dc = (a == 1) ? swz_chunk(c) : c;
            cp_async16(&sm[wv * 5120 + a * 1024 + st * 64 + dc * 4],
                       arrs[a] + base + (size_t)(wv * 16 + st) * 64 + c * 4);
        }
    cp_commit();
    cp_wait0();
    BAR_ALL();
    if (tid >= 128) wkv_precompute(0, tid - 128, sm);
    BAR_ALL();
    if (tid < 128) wkv_producer(tid, sm);
    else           wkv_helper(tid - 128, sm, arrs, base, out, b, h);
}

// ============================================================================
__device__ __forceinline__ void ssd_chunk_body(
    int blk, int tid, float* sm,
    const float* __restrict__ X, const float* __restrict__ A,
    const float* __restrict__ Bm, const float* __restrict__ Cm)
{
    float* sB = sm;
    float* sG = sm + 64 * 65;
    float* sX = sm + 2 * 64 * 65;
    float* s_cum = sX + 4096;
    float* s_eA  = s_cum + 64;
    float* s_ieA = s_eA + 64;
    const int h = blk & 15, cc = (blk >> 4) & 31, b = blk >> 9;

    const size_t gbase = ((size_t)(b * 2048 + cc * 64) * 16 + h) * 64;
#pragma unroll
    for (int u = 0; u < 4; ++u) {
        int idx4 = u * 256 + tid;
        int l = idx4 >> 4, n4 = (idx4 & 15) * 4;
        size_t go = gbase + (size_t)l * 1024 + n4;
        float4 bv = *(const float4*)(Bm + go);
        float4 cv = *(const float4*)(Cm + go);
        float4 xv = *(const float4*)(X + go);
        float* pb = sB + l * 65 + n4;
        pb[0] = bv.x; pb[1] = bv.y; pb[2] = bv.z; pb[3] = bv.w;
        float* pc = sG + l * 65 + n4;
        pc[0] = cv.x; pc[1] = cv.y; pc[2] = cv.z; pc[3] = cv.w;
        *(float4*)(sX + l * 64 + n4) = xv;
    }
    if (tid < 64) {
        float x = A[(size_t)(b * 2048 + cc * 64 + tid) * 16 + h];
#pragma unroll
        for (int o = 1; o < 32; o <<= 1) {
            float t = __shfl_up_sync(0xffffffffu, x, o);
            if ((tid & 31) >= o) x += t;
        }
        s_cum[tid] = x;
    }
    __syncthreads();
    if (tid < 64) {
        float x = s_cum[tid] + ((tid >= 32) ? s_cum[31] : 0.f);
        float e = expf(x);
        s_eA[tid] = e;
        s_ieA[tid] = expf(-x);
        g_eA[(size_t)blk * 64 + tid] = e;
        if (tid == 63) g_expsA[(b * 16 + h) * 32 + cc] = e;
    }
    __syncthreads();

    const int tl = tid >> 4, ts = tid & 15;
    const int r0 = tl * 4, c0 = ts * 4;
    float g[4][4];
#pragma unroll
    for (int ii = 0; ii < 4; ++ii)
#pragma unroll
        for (int jj = 0; jj < 4; ++jj) g[ii][jj] = 0.f;
    for (int n = 0; n < 64; ++n) {
        float cl[4], bsv[4];
#pragma unroll
        for (int ii = 0; ii < 4; ++ii) cl[ii] = sG[(r0 + ii) * 65 + n];
#pragma unroll
        for (int jj = 0; jj < 4; ++jj) bsv[jj] = sB[(c0 + jj) * 65 + n];
#pragma unroll
        for (int ii = 0; ii < 4; ++ii)
#pragma unroll
            for (int jj = 0; jj < 4; ++jj) g[ii][jj] = fmaf(cl[ii], bsv[jj], g[ii][jj]);
    }
    __syncthreads();
#pragma unroll
    for (int ii = 0; ii < 4; ++ii) {
        int l = r0 + ii;
        float el = s_eA[l];
#pragma unroll
        for (int jj = 0; jj < 4; ++jj) {
            int s = c0 + jj;
            sG[l * 65 + s] = (s <= l) ? g[ii][jj] * el * s_ieA[s] : 0.f;
        }
    }
    __syncthreads();

    float y[4][4];
#pragma unroll
    for (int ii = 0; ii < 4; ++ii)
#pragma unroll
        for (int jj = 0; jj < 4; ++jj) y[ii][jj] = 0.f;
    for (int s = 0; s < 64; ++s) {
        float4 xv = *(const float4*)(sX + s * 64 + c0);
        float gl[4];
#pragma unroll
        for (int ii = 0; ii < 4; ++ii) gl[ii] = sG[(r0 + ii) * 65 + s];
#pragma unroll
        for (int ii = 0; ii < 4; ++ii) {
            y[ii][0] = fmaf(gl[ii], xv.x, y[ii][0]);
            y[ii][1] = fmaf(gl[ii], xv.y, y[ii][1]);
            y[ii][2] = fmaf(gl[ii], xv.z, y[ii][2]);
            y[ii][3] = fmaf(gl[ii], xv.w, y[ii][3]);
        }
    }
#pragma unroll
    for (int ii = 0; ii < 4; ++ii) {
        int l = r0 + ii;
        *(float4*)(g_yd + (size_t)(b * 2048 + cc * 64 + l) * 1024 + h * 64 + c0) =
            make_float4(y[ii][0], y[ii][1], y[ii][2], y[ii][3]);
    }

    float stt[4][4];
#pragma unroll
    for (int ii = 0; ii < 4; ++ii)
#pragma unroll
        for (int jj = 0; jj < 4; ++jj) stt[ii][jj] = 0.f;
    const float eA63 = s_eA[63];
    for (int l = 0; l < 64; ++l) {
        float ds = eA63 * s_ieA[l];
        float4 xv = *(const float4*)(sX + l * 64 + r0);
        float xw[4] = { xv.x * ds, xv.y * ds, xv.z * ds, xv.w * ds };
        float bv[4];
#pragma unroll
        for (int jj = 0; jj < 4; ++jj) bv[jj] = sB[l * 65 + c0 + jj];
#pragma unroll
        for (int ii = 0; ii < 4; ++ii)
#pragma unroll
            for (int jj = 0; jj < 4; ++jj) stt[ii][jj] = fmaf(xw[ii], bv[jj], stt[ii][jj]);
    }
#pragma unroll
    for (int ii = 0; ii < 4; ++ii)
        *(float4*)(g_states + (size_t)blk * 4096 + (size_t)(r0 + ii) * 64 + c0) =
            make_float4(stt[ii][0], stt[ii][1], stt[ii][2], stt[ii][3]);
}

// off tile: g_yd[tile] += eA[l] * (C . R^T)
__device__ __forceinline__ void ssd_off_tile(
    int blk, int tid, float* sm, const float* __restrict__ Cm)
{
    float* sC  = sm;
    float* sR  = sm + 64 * 65;
    float* s_e = sm + 2 * 64 * 65;
    const int h = blk & 15, cc = (blk >> 4) & 31, b = blk >> 9;

    const size_t gbase = ((size_t)(b * 2048 + cc * 64) * 16 + h) * 64;
#pragma unroll
    for (int u = 0; u < 4; ++u) {
        int idx4 = u * 256 + tid;
        int l = idx4 >> 4, n4 = (idx4 & 15) * 4;
        float4 cv = *(const float4*)(Cm + gbase + (size_t)l * 1024 + n4);
        float4 rv = *(const float4*)(g_R + (size_t)blk * 4096 + (size_t)idx4 * 4);
        float* pc = sC + l * 65 + n4;
        pc[0] = cv.x; pc[1] = cv.y; pc[2] = cv.z; pc[3] = cv.w;
        float* pr = sR + l * 65 + n4;
        pr[0] = rv.x; pr[1] = rv.y; pr[2] = rv.z; pr[3] = rv.w;
    }
    if (tid < 64) s_e[tid] = g_eA[(size_t)blk * 64 + tid];
    __syncthreads();

    const int tl = tid >> 4, ts = tid & 15;
    const int l0 = tl * 4, p0 = ts * 4;
    float acc[4][4];
#pragma unroll
    for (int ii = 0; ii < 4; ++ii)
#pragma unroll
        for (int jj = 0; jj < 4; ++jj) acc[ii][jj] = 0.f;
    for (int n = 0; n < 64; ++n) {
        float cl[4], rv[4];
#pragma unroll
        for (int ii = 0; ii < 4; ++ii) cl[ii] = sC[(l0 + ii) * 65 + n];
#pragma unroll
        for (int jj = 0; jj < 4; ++jj) rv[jj] = sR[(p0 + jj) * 65 + n];
#pragma unroll
        for (int ii = 0; ii < 4; ++ii)
#pragma unroll
            for (int jj = 0; jj < 4; ++jj) acc[ii][jj] = fmaf(cl[ii], rv[jj], acc[ii][jj]);
    }
#pragma unroll
    for (int ii = 0; ii < 4; ++ii) {
        int l = l0 + ii;
        float e = s_e[l];
        size_t ofs = (size_t)(b * 2048 + cc * 64 + l) * 1024 + h * 64 + p0;
        float4* po = (float4*)(g_yd + ofs);
        float4 o = *po;
        o.x += e * acc[ii][0];
        o.y += e * acc[ii][1];
        o.z += e * acc[ii][2];
        o.w += e * acc[ii][3];
        *po = o;
    }
    __syncthreads();
}

// ============================================================================
__global__ void __launch_bounds__(256, 1) fused_kernel(
    const float* __restrict__ X, const float* __restrict__ A,
    const float* __restrict__ Bm, const float* __restrict__ Cm,
    const float* __restrict__ rr, const float* __restrict__ kk,
    const float* __restrict__ vv, const float* __restrict__ ww,
    const float* __restrict__ bo, float* __restrict__ out)
{
    extern __shared__ float sm[];
    const int tid = threadIdx.x;
    if (blockIdx.x < 32) {
        wkv_block(blockIdx.x, tid, sm, rr, kk, vv, ww, bo, out);
        return;
    }
    const int blk = blockIdx.x - 32;
    ssd_chunk_body(blk, tid, sm, X, A, Bm, Cm);
    __threadfence();
    __syncthreads();
    if (tid == 0) atomicAdd(&g_cnt1, 1u);
    if (blk >= 64) return;

    if (tid == 0) { while (atomicAdd(&g_cnt1, 0u) < 1024u) __nanosleep(256); }
    __syncthreads();
    __threadfence();

    {
        const int bh = blk >> 1;
        const int b = bh >> 4, h = bh & 15;
        const int e0 = (blk & 1) * 2048 + tid * 8;
        const float* es = g_expsA + bh * 32;
        float4 R0 = make_float4(0.f, 0.f, 0.f, 0.f);
        float4 R1 = make_float4(0.f, 0.f, 0.f, 0.f);
#pragma unroll 1
        for (int c = 0; c < 32; ++c) {
            size_t idx = (size_t)(b * 512 + c * 16 + h) * 4096 + e0;
            *(float4*)(g_R + idx)     = R0;
            *(float4*)(g_R + idx + 4) = R1;
            const float s = es[c];
            float4 s0 = *(const float4*)(g_states + idx);
            float4 s1 = *(const float4*)(g_states + idx + 4);
            R0.x = fmaf(R0.x, s, s0.x); R0.y = fmaf(R0.y, s, s0.y);
            R0.z = fmaf(R0.z, s, s0.z); R0.w = fmaf(R0.w, s, s0.w);
            R1.x = fmaf(R1.x, s, s1.x); R1.y = fmaf(R1.y, s, s1.y);
            R1.z = fmaf(R1.z, s, s1.z); R1.w = fmaf(R1.w, s, s1.w);
        }
    }
    __threadfence();
    __syncthreads();
    if (tid == 0) {
        atomicAdd(&g_cnt2, 1u);
        while (atomicAdd(&g_cnt2, 0u) < 64u) __nanosleep(256);
    }
    __syncthreads();
    __threadfence();

#pragma unroll 1
    for (int t = 0; t < 16; ++t)
        ssd_off_tile(blk * 16 + t, tid, sm, Cm);
}

__global__ void __launch_bounds__(256) add_kernel(float* __restrict__ out)
{
    const size_t i0 = (size_t)blockIdx.x * 512 + threadIdx.x;   // float4 index
#pragma unroll
    for (int r = 0; r < 2; ++r) {
        const size_t i = i0 + r * 256;
        float4 o = ((float4*)out)[i];
        float4 yd = ((const float4*)g_yd)[i];
        o.x += yd.x; o.y += yd.y; o.z += yd.z; o.w += yd.w;
        ((float4*)out)[i] = o;
    }
    if (blockIdx.x == 0 && threadIdx.x == 0) { g_cnt1 = 0u; g_cnt2 = 0u; }
}

extern "C" void kernel_launch(void* const* d_in, const int* in_sizes, int n_in,
                              void* d_out, int out_size)
{
    (void)in_sizes; (void)n_in; (void)out_size;
    const float* X  = (const float*)d_in[0];
    const float* A  = (const float*)d_in[1];
    const float* B  = (const float*)d_in[2];
    const float* C  = (const float*)d_in[3];
    const float* r  = (const float*)d_in[4];
    const float* k  = (const float*)d_in[5];
    const float* v  = (const float*)d_in[6];
    const float* w  = (const float*)d_in[7];
    const float* bo = (const float*)d_in[8];
    float* out = (float*)d_out;

    const int FUSED_SMEM = WKV_SMEM_FLOATS * 4;   // 107072 B
    cudaFuncSetAttribute(fused_kernel,
                         cudaFuncAttributeMaxDynamicSharedMemorySize, FUSED_SMEM);

    fused_kernel<<<1056, 256, FUSED_SMEM>>>(X, A, B, C, r, k, v, w, bo, out);
    add_kernel<<<(2 * 2048 * 1024) / (4 * 512), 256>>>(out);
}

// round 17
// speedup vs baseline: 1.6150x; 1.0464x over previous
#include <cuda_runtime.h>
#include <cstdint>
#include <cstddef>
typedef unsigned long long ull;

__device__ float g_states[2*32*16*64*64];
__device__ float g_R[2*32*16*64*64];
__device__ float g_eA[1024*64];
__device__ float g_expsA[32*32];
__device__ float g_yd[2*2048*1024];     // Y_diag, then += e*C.R^T (SSD total)
__device__ unsigned g_cnt1;             // chunk-done counter (reset by add kernel)
__device__ unsigned g_cnt2;             // scan-done counter

__device__ __forceinline__ void cp_async16(float* dst, const float* src) {
    unsigned s = (unsigned)__cvta_generic_to_shared(dst);
    asm volatile("cp.async.cg.shared.global [%0], [%1], 16;\n" :: "r"(s), "l"(src));
}
__device__ __forceinline__ void cp_commit() { asm volatile("cp.async.commit_group;\n"); }
__device__ __forceinline__ void cp_wait1()  { asm volatile("cp.async.wait_group 1;\n" ::: "memory"); }
__device__ __forceinline__ void cp_wait0()  { asm volatile("cp.async.wait_group 0;\n" ::: "memory"); }
__device__ __forceinline__ ull f2fma(ull a, ull b, ull c) {
    ull d; asm("fma.rn.f32x2 %0, %1, %2, %3;" : "=l"(d) : "l"(a), "l"(b), "l"(c)); return d;
}
__device__ __forceinline__ ull f2mul(ull a, ull b) {
    ull d; asm("mul.rn.f32x2 %0, %1, %2;" : "=l"(d) : "l"(a), "l"(b)); return d;
}
__device__ __forceinline__ ull f2add(ull a, ull b) {
    ull d; asm("add.rn.f32x2 %0, %1, %2;" : "=l"(d) : "l"(a), "l"(b)); return d;
}
__device__ __forceinline__ ull pk2(float lo, float hi) {
    ull r; asm("mov.b64 %0, {%1, %2};" : "=l"(r) : "f"(lo), "f"(hi)); return r;
}
__device__ __forceinline__ float2 upk2(ull p) {
    float2 f; asm("mov.b64 {%0, %1}, %2;" : "=f"(f.x), "=f"(f.y) : "l"(p)); return f;
}
__device__ __forceinline__ int swz_chunk(int c) { return ((c & 7) << 1) | (c >> 3); }
__device__ __forceinline__ int swz_pos(int j)   { return (swz_chunk(j >> 2) << 2) | (j & 3); }

#define BAR_ALL()  asm volatile("bar.sync 1, 256;" ::: "memory")
#define BAR_PROD() asm volatile("bar.sync 2, 128;" ::: "memory")
#define BAR_HELP() asm volatile("bar.sync 3, 128;" ::: "memory")

#define OFF_DL 20480
#define OFF_DK 22528
#define OFF_NW 22544
#define OFF_C2 24592
#define OFF_WT 26640
#define WKV_SMEM_FLOATS 26768

__device__ __forceinline__ void wkv_precompute(int wn, int tid, float* sm)
{
    if (tid >= 64) return;
    const int j = tid, pj = swz_pos(j);
    const float* pr = sm + (wn & 3) * 5120;
    float* nw = sm + OFF_NW + (wn & 1) * 1024;
    float* c2 = sm + OFF_C2 + (wn & 1) * 1024;
    float W = 1.f;
#pragma unroll
    for (int t = 0; t < 16; ++t) {
        nw[t * 64 + j] = -W;
        W *= pr[3072 + t * 64 + j];
        c2[t * 64 + j] = __fdividef(pr[4096 + t * 64 + j] * pr[1024 + t * 64 + pj], W);
    }
    sm[OFF_WT + (wn & 1) * 64 + j] = W;
}

__device__ __forceinline__ void wkv_producer(int tid, float* sm)
{
    const int i = tid >> 1, h2 = tid & 1;
    const int pos_i = swz_pos(i);
    ull S2[16];
#pragma unroll
    for (int u = 0; u < 16; ++u) S2[u] = 0ull;

#pragma unroll 1
    for (int win = 0; win < 128; ++win) {
        const float* pr = sm + (win & 3) * 5120;
        float* dl = sm + OFF_DL + (win & 1) * 1024;
        const float* nw = sm + OFF_NW + (win & 1) * 1024;
        const float* c2 = sm + OFF_C2 + (win & 1) * 1024;

#pragma unroll 4
        for (int s = 0; s < 8; ++s) {
            const int st0 = 2 * s, st1 = st0 + 1;
            const float* k0s = pr + 1024 + st0 * 64;
            const float* k1s = pr + 1024 + st1 * 64;

            // scalar row operands first (independent of S2 -> issue early)
            const float v0  = pr[2048 + st0*64 + i];
            const float nW0 = nw[st0*64 + i];
            const float c0  = c2[st0*64 + i];
            const float v1  = pr[2048 + st1*64 + i];
            const float nW1 = nw[st1*64 + i];
            const float c1  = c2[st1*64 + i];

            ull ka[16], kb[16];
#pragma unroll
            for (int u = 0; u < 8; ++u) {
                float4 qa = *(const float4*)(k0s + (2 * u + h2) * 4);
                float4 qb = *(const float4*)(k1s + (2 * u + h2) * 4);
                ka[2*u] = *(ull*)&qa.x; ka[2*u+1] = *(ull*)&qa.z;
                kb[2*u] = *(ull*)&qb.x; kb[2*u+1] = *(ull*)&qb.z;
            }
            ull a0 = f2mul(S2[0], ka[0]);
            ull a1 = f2mul(S2[1], ka[1]);
            ull a2 = f2mul(S2[2], ka[2]);
            ull a3 = f2mul(S2[3], ka[3]);
            ull e0 = f2mul(S2[0], kb[0]);
            ull e1 = f2mul(S2[1], kb[1]);
            ull e2 = f2mul(S2[2], kb[2]);
            ull e3 = f2mul(S2[3], kb[3]);
#pragma unroll
            for (int u = 1; u < 4; ++u) {
                a0 = f2fma(S2[4*u+0], ka[4*u+0], a0);
                a1 = f2fma(S2[4*u+1], ka[4*u+1], a1);
                a2 = f2fma(S2[4*u+2], ka[4*u+2], a2);
                a3 = f2fma(S2[4*u+3], ka[4*u+3], a3);
                e0 = f2fma(S2[4*u+0], kb[4*u+0], e0);
                e1 = f2fma(S2[4*u+1], kb[4*u+1], e1);
                e2 = f2fma(S2[4*u+2], kb[4*u+2], e2);
                e3 = f2fma(S2[4*u+3], kb[4*u+3], e3);
            }
            a0 = f2add(a0, a1); a2 = f2add(a2, a3); a0 = f2add(a0, a2);
            e0 = f2add(e0, e1); e2 = f2add(e2, e3); e0 = f2add(e0, e2);
            float2 af = upk2(a0), ef = upk2(e0);
            float accA = af.x + af.y;
            float accB = ef.x + ef.y;
            accA += __shfl_xor_sync(0xffffffffu, accA, 1);
            accB += __shfl_xor_sync(0xffffffffu, accB, 1);

            dl[st0*64 + pos_i] = fmaf(nW0, accA, v0);
            const ull c02 = pk2(c0, c0);
            BAR_PROD();

            ull u0 = 0ull, u1 = 0ull, u2 = 0ull, u3 = 0ull;
            {
                float4 dq0 = *(const float4*)(dl + st0*64 + (0 + h2)*4);
                float4 dq1 = *(const float4*)(dl + st0*64 + (2 + h2)*4);
                float4 dq2 = *(const float4*)(dl + st0*64 + (4 + h2)*4);
                float4 dq3 = *(const float4*)(dl + st0*64 + (6 + h2)*4);
                float4 dq4 = *(const float4*)(dl + st0*64 + (8 + h2)*4);
                float4 dq5 = *(const float4*)(dl + st0*64 + (10 + h2)*4);
                float4 dq6 = *(const float4*)(dl + st0*64 + (12 + h2)*4);
                float4 dq7 = *(const float4*)(dl + st0*64 + (14 + h2)*4);
                ull t0, t1;
#define UPD(Q, bu, ux, uy) \
                t0 = *(ull*)&Q.x; t1 = *(ull*)&Q.z; \
                ux = f2fma(t0, kb[2*(bu)],   ux); \
                uy = f2fma(t1, kb[2*(bu)+1], uy); \
                S2[2*(bu)]   = f2fma(c02, t0, S2[2*(bu)]); \
                S2[2*(bu)+1] = f2fma(c02, t1, S2[2*(bu)+1]);
                UPD(dq0, 0, u0, u1) UPD(dq1, 1, u2, u3)
                UPD(dq2, 2, u0, u1) UPD(dq3, 3, u2, u3)
                UPD(dq4, 4, u0, u1) UPD(dq5, 5, u2, u3)
                UPD(dq6, 6, u0, u1) UPD(dq7, 7, u2, u3)
#undef UPD
            }
            u0 = f2add(u0, u1); u2 = f2add(u2, u3); u0 = f2add(u0, u2);
            float2 uf = upk2(u0);
            float uu = uf.x + uf.y;
            uu += __shfl_xor_sync(0xffffffffu, uu, 1);

            dl[st1*64 + pos_i] = fmaf(nW1, fmaf(c0, uu, accB), v1);
            const ull c12 = pk2(c1, c1);
            BAR_PROD();

#pragma unroll
            for (int u = 0; u < 8; ++u) {
                float4 dq = *(const float4*)(dl + st1*64 + (2*u + h2)*4);
                S2[2*u]   = f2fma(c12, *(ull*)&dq.x, S2[2*u]);
                S2[2*u+1] = f2fma(c12, *(ull*)&dq.z, S2[2*u+1]);
            }
        }
        const float wti = sm[OFF_WT + (win & 1) * 64 + i];
        const ull w2 = pk2(wti, wti);
#pragma unroll
        for (int u = 0; u < 16; ++u) S2[u] = f2mul(S2[u], w2);
        BAR_ALL();
    }
}

__device__ __forceinline__ void wkv_emit_window(
    int wn, int tid, float* sm, float* __restrict__ out, int b, int h)
{
    const float* pr = sm + (wn & 3) * 5120;
    const float* dl = sm + OFF_DL + (wn & 1) * 1024;
    float* s_dk = sm + OFF_DK;
    const int lane = tid & 31, wid = tid >> 5;
#pragma unroll
    for (int rep = 0; rep < 4; ++rep) {
        const int st = rep * 4 + wid;
        const int pp = swz_chunk(lane >> 1) * 4 + (lane & 1) * 2;
        float2 kv  = *(const float2*)(pr + 1024 + st * 64 + pp);
        float2 dl2 = *(const float2*)(dl + st * 64 + pp);
        float pd = fmaf(dl2.x, kv.x, dl2.y * kv.y);
#pragma unroll
        for (int off = 16; off > 0; off >>= 1)
            pd += __shfl_xor_sync(0xffffffffu, pd, off);
        if (lane == 0) s_dk[st] = pd;
    }
    BAR_HELP();
#pragma unroll
    for (int rep = 0; rep < 4; ++rep) {
        const int idx = rep * 128 + tid;
        const int st = idx >> 5, cp2 = idx & 31;
        const int col = cp2 * 2;
        const int pp = swz_chunk(cp2 >> 1) * 4 + (cp2 & 1) * 2;
        float2 dv = *(const float2*)(dl + st * 64 + pp);
        float2 k_ = *(const float2*)(pr + 1024 + st * 64 + pp);
        float2 r_ = *(const float2*)(pr + st * 64 + col);
        float2 v_ = *(const float2*)(pr + 2048 + st * 64 + col);
        float2 w_ = *(const float2*)(pr + 3072 + st * 64 + col);
        float2 b_ = *(const float2*)(pr + 4096 + st * 64 + col);
        const float dk = s_dk[st];
        float2 y;
        y.x = r_.x * fmaf(b_.x * k_.x, dk, w_.x * (v_.x - dv.x));
        y.y = r_.y * fmaf(b_.y * k_.y, dk, w_.y * (v_.y - dv.y));
        *(float2*)(out + (size_t)(b * 2048 + wn * 16 + st) * 1024 + h * 64 + col) = y;
    }
}

__device__ __forceinline__ void wkv_helper(
    int tid, float* sm, const float* const* arrs, size_t base,
    float* __restrict__ out, int b, int h)
{
#pragma unroll 1
    for (int win = 0; win < 128; ++win) {
        if (win + 2 < 128) {
            const int dst = ((win + 2) & 3) * 5120;
#pragma unroll
            for (int a = 0; a < 5; ++a)
#pragma unroll
                for (int rep = 0; rep < 2; ++rep) {
                    int x = rep * 128 + tid;
                    int st = x >> 4, c = x & 15;
                    int dc = (a == 1) ? swz_chunk(c) : c;
                    cp_async16(&sm[dst + a * 1024 + st * 64 + dc * 4],
                               arrs[a] + base + (size_t)((win + 2) * 16 + st) * 64 + c * 4);
                }
            cp_commit();
        }
        if (win >= 1) wkv_emit_window(win - 1, tid, sm, out, b, h);
        if (win >= 126) cp_wait0(); else cp_wait1();
        BAR_HELP();   // fence all helpers' retired cp.async before cross-reads
        if (win + 1 < 128) wkv_precompute(win + 1, tid, sm);
        BAR_ALL();
    }
    wkv_emit_window(127, tid, sm, out, b, h);
}

__device__ __forceinline__ void wkv_block(
    int bh, int tid, float* sm,
    const float* __restrict__ rr, const float* __restrict__ kk_g,
    const float* __restrict__ vv_g, const float* __restrict__ ww_g,
    const float* __restrict__ bo_g, float* __restrict__ out)
{
    const int b = bh >> 4, h = bh & 15;
    const size_t base = (size_t)bh * 2048 * 64;
    const float* arrs[5] = { rr, kk_g, vv_g, ww_g, bo_g };
#pragma unroll
    for (int wv = 0; wv < 2; ++wv)
#pragma unroll
        for (int a = 0; a < 5; ++a) {
            int st = tid >> 4, c = tid & 15;
            int dc = (a == 1) ? swz_chunk(c) : c;
            cp_async16(&sm[wv * 5120 + a * 1024 + st * 64 + dc * 4],
                       arrs[a] + base + (size_t)(wv * 16 + st) * 64 + c * 4);
        }
    cp_commit();
    cp_wait0();
    BAR_ALL();
    if (tid >= 128) wkv_precompute(0, tid - 128, sm);
    BAR_ALL();
    if (tid < 128) wkv_producer(tid, sm);
    else           wkv_helper(tid - 128, sm, arrs, base, out, b, h);
}

// ============================================================================
__device__ __forceinline__ void ssd_chunk_body(
    int blk, int tid, float* sm,
    const float* __restrict__ X, const float* __restrict__ A,
    const float* __restrict__ Bm, const float* __restrict__ Cm)
{
    float* sB = sm;
    float* sG = sm + 64 * 65;
    float* sX = sm + 2 * 64 * 65;
    float* s_cum = sX + 4096;
    float* s_eA  = s_cum + 64;
    float* s_ieA = s_eA + 64;
    const int h = blk & 15, cc = (blk >> 4) & 31, b = blk >> 9;

    const size_t gbase = ((size_t)(b * 2048 + cc * 64) * 16 + h) * 64;
#pragma unroll
    for (int u = 0; u < 4; ++u) {
        int idx4 = u * 256 + tid;
        int l = idx4 >> 4, n4 = (idx4 & 15) * 4;
        size_t go = gbase + (size_t)l * 1024 + n4;
        float4 bv = *(const float4*)(Bm + go);
        float4 cv = *(const float4*)(Cm + go);
        float4 xv = *(const float4*)(X + go);
        float* pb = sB + l * 65 + n4;
        pb[0] = bv.x; pb[1] = bv.y; pb[2] = bv.z; pb[3] = bv.w;
        float* pc = sG + l * 65 + n4;
        pc[0] = cv.x; pc[1] = cv.y; pc[2] = cv.z; pc[3] = cv.w;
        *(float4*)(sX + l * 64 + n4) = xv;
    }
    if (tid < 64) {
        float x = A[(size_t)(b * 2048 + cc * 64 + tid) * 16 + h];
#pragma unroll
        for (int o = 1; o < 32; o <<= 1) {
            float t = __shfl_up_sync(0xffffffffu, x, o);
            if ((tid & 31) >= o) x += t;
        }
        s_cum[tid] = x;
    }
    __syncthreads();
    if (tid < 64) {
        float x = s_cum[tid] + ((tid >= 32) ? s_cum[31] : 0.f);
        float e = expf(x);
        s_eA[tid] = e;
        s_ieA[tid] = expf(-x);
        g_eA[(size_t)blk * 64 + tid] = e;
        if (tid == 63) g_expsA[(b * 16 + h) * 32 + cc] = e;
    }
    __syncthreads();

    const int tl = tid >> 4, ts = tid & 15;
    const int r0 = tl * 4, c0 = ts * 4;
    float g[4][4];
#pragma unroll
    for (int ii = 0; ii < 4; ++ii)
#pragma unroll
        for (int jj = 0; jj < 4; ++jj) g[ii][jj] = 0.f;
    for (int n = 0; n < 64; ++n) {
        float cl[4], bsv[4];
#pragma unroll
        for (int ii = 0; ii < 4; ++ii) cl[ii] = sG[(r0 + ii) * 65 + n];
#pragma unroll
        for (int jj = 0; jj < 4; ++jj) bsv[jj] = sB[(c0 + jj) * 65 + n];
#pragma unroll
        for (int ii = 0; ii < 4; ++ii)
#pragma unroll
            for (int jj = 0; jj < 4; ++jj) g[ii][jj] = fmaf(cl[ii], bsv[jj], g[ii][jj]);
    }
    __syncthreads();
#pragma unroll
    for (int ii = 0; ii < 4; ++ii) {
        int l = r0 + ii;
        float el = s_eA[l];
#pragma unroll
        for (int jj = 0; jj < 4; ++jj) {
            int s = c0 + jj;
            sG[l * 65 + s] = (s <= l) ? g[ii][jj] * el * s_ieA[s] : 0.f;
        }
    }
    __syncthreads();

    float y[4][4];
#pragma unroll
    for (int ii = 0; ii < 4; ++ii)
#pragma unroll
        for (int jj = 0; jj < 4; ++jj) y[ii][jj] = 0.f;
    for (int s = 0; s < 64; ++s) {
        float4 xv = *(const float4*)(sX + s * 64 + c0);
        float gl[4];
#pragma unroll
        for (int ii = 0; ii < 4; ++ii) gl[ii] = sG[(r0 + ii) * 65 + s];
#pragma unroll
        for (int ii = 0; ii < 4; ++ii) {
            y[ii][0] = fmaf(gl[ii], xv.x, y[ii][0]);
            y[ii][1] = fmaf(gl[ii], xv.y, y[ii][1]);
            y[ii][2] = fmaf(gl[ii], xv.z, y[ii][2]);
            y[ii][3] = fmaf(gl[ii], xv.w, y[ii][3]);
        }
    }
#pragma unroll
    for (int ii = 0; ii < 4; ++ii) {
        int l = r0 + ii;
        *(float4*)(g_yd + (size_t)(b * 2048 + cc * 64 + l) * 1024 + h * 64 + c0) =
            make_float4(y[ii][0], y[ii][1], y[ii][2], y[ii][3]);
    }

    float stt[4][4];
#pragma unroll
    for (int ii = 0; ii < 4; ++ii)
#pragma unroll
        for (int jj = 0; jj < 4; ++jj) stt[ii][jj] = 0.f;
    const float eA63 = s_eA[63];
    for (int l = 0; l < 64; ++l) {
        float ds = eA63 * s_ieA[l];
        float4 xv = *(const float4*)(sX + l * 64 + r0);
        float xw[4] = { xv.x * ds, xv.y * ds, xv.z * ds, xv.w * ds };
        float bv[4];
#pragma unroll
        for (int jj = 0; jj < 4; ++jj) bv[jj] = sB[l * 65 + c0 + jj];
#pragma unroll
        for (int ii = 0; ii < 4; ++ii)
#pragma unroll
            for (int jj = 0; jj < 4; ++jj) stt[ii][jj] = fmaf(xw[ii], bv[jj], stt[ii][jj]);
    }
#pragma unroll
    for (int ii = 0; ii < 4; ++ii)
        *(float4*)(g_states + (size_t)blk * 4096 + (size_t)(r0 + ii) * 64 + c0) =
            make_float4(stt[ii][0], stt[ii][1], stt[ii][2], stt[ii][3]);
}

// off tile: g_yd[tile] += eA[l] * (C . R^T)
__device__ __forceinline__ void ssd_off_tile(
    int blk, int tid, float* sm, const float* __restrict__ Cm)
{
    float* sC  = sm;
    float* sR  = sm + 64 * 65;
    float* s_e = sm + 2 * 64 * 65;
    const int h = blk & 15, cc = (blk >> 4) & 31, b = blk >> 9;

    const size_t gbase = ((size_t)(b * 2048 + cc * 64) * 16 + h) * 64;
#pragma unroll
    for (int u = 0; u < 4; ++u) {
        int idx4 = u * 256 + tid;
        int l = idx4 >> 4, n4 = (idx4 & 15) * 4;
        float4 cv = *(const float4*)(Cm + gbase + (size_t)l * 1024 + n4);
        float4 rv = *(const float4*)(g_R + (size_t)blk * 4096 + (size_t)idx4 * 4);
        float* pc = sC + l * 65 + n4;
        pc[0] = cv.x; pc[1] = cv.y; pc[2] = cv.z; pc[3] = cv.w;
        float* pr = sR + l * 65 + n4;
        pr[0] = rv.x; pr[1] = rv.y; pr[2] = rv.z; pr[3] = rv.w;
    }
    if (tid < 64) s_e[tid] = g_eA[(size_t)blk * 64 + tid];
    __syncthreads();

    const int tl = tid >> 4, ts = tid & 15;
    const int l0 = tl * 4, p0 = ts * 4;
    float acc[4][4];
#pragma unroll
    for (int ii = 0; ii < 4; ++ii)
#pragma unroll
        for (int jj = 0; jj < 4; ++jj) acc[ii][jj] = 0.f;
    for (int n = 0; n < 64; ++n) {
        float cl[4], rv[4];
#pragma unroll
        for (int ii = 0; ii < 4; ++ii) cl[ii] = sC[(l0 + ii) * 65 + n];
#pragma unroll
        for (int jj = 0; jj < 4; ++jj) rv[jj] = sR[(p0 + jj) * 65 + n];
#pragma unroll
        for (int ii = 0; ii < 4; ++ii)
#pragma unroll
            for (int jj = 0; jj < 4; ++jj) acc[ii][jj] = fmaf(cl[ii], rv[jj], acc[ii][jj]);
    }
#pragma unroll
    for (int ii = 0; ii < 4; ++ii) {
        int l = l0 + ii;
        float e = s_e[l];
        size_t ofs = (size_t)(b * 2048 + cc * 64 + l) * 1024 + h * 64 + p0;
        float4* po = (float4*)(g_yd + ofs);
        float4 o = *po;
        o.x += e * acc[ii][0];
        o.y += e * acc[ii][1];
        o.z += e * acc[ii][2];
        o.w += e * acc[ii][3];
        *po = o;
    }
    __syncthreads();
}

// ============================================================================
__global__ void __launch_bounds__(256, 1) fused_kernel(
    const float* __restrict__ X, const float* __restrict__ A,
    const float* __restrict__ Bm, const float* __restrict__ Cm,
    const float* __restrict__ rr, const float* __restrict__ kk,
    const float* __restrict__ vv, const float* __restrict__ ww,
    const float* __restrict__ bo, float* __restrict__ out)
{
    extern __shared__ float sm[];
    const int tid = threadIdx.x;
    if (blockIdx.x < 32) {
        wkv_block(blockIdx.x, tid, sm, rr, kk, vv, ww, bo, out);
        return;
    }
    const int blk = blockIdx.x - 32;
    ssd_chunk_body(blk, tid, sm, X, A, Bm, Cm);
    __threadfence();
    __syncthreads();
    if (tid == 0) atomicAdd(&g_cnt1, 1u);
    if (blk >= 64) return;

    if (tid == 0) { while (atomicAdd(&g_cnt1, 0u) < 1024u) __nanosleep(256); }
    __syncthreads();
    __threadfence();

    {
        const int bh = blk >> 1;
        const int b = bh >> 4, h = bh & 15;
        const int e0 = (blk & 1) * 2048 + tid * 8;
        const float* es = g_expsA + bh * 32;
        float4 R0 = make_float4(0.f, 0.f, 0.f, 0.f);
        float4 R1 = make_float4(0.f, 0.f, 0.f, 0.f);
#pragma unroll 1
        for (int c = 0; c < 32; ++c) {
            size_t idx = (size_t)(b * 512 + c * 16 + h) * 4096 + e0;
            *(float4*)(g_R + idx)     = R0;
            *(float4*)(g_R + idx + 4) = R1;
            const float s = es[c];
            float4 s0 = *(const float4*)(g_states + idx);
            float4 s1 = *(const float4*)(g_states + idx + 4);
            R0.x = fmaf(R0.x, s, s0.x); R0.y = fmaf(R0.y, s, s0.y);
            R0.z = fmaf(R0.z, s, s0.z); R0.w = fmaf(R0.w, s, s0.w);
            R1.x = fmaf(R1.x, s, s1.x); R1.y = fmaf(R1.y, s, s1.y);
            R1.z = fmaf(R1.z, s, s1.z); R1.w = fmaf(R1.w, s, s1.w);
        }
    }
    __threadfence();
    __syncthreads();
    if (tid == 0) {
        atomicAdd(&g_cnt2, 1u);
        while (atomicAdd(&g_cnt2, 0u) < 64u) __nanosleep(256);
    }
    __syncthreads();
    __threadfence();

#pragma unroll 1
    for (int t = 0; t < 16; ++t)
        ssd_off_tile(blk * 16 + t, tid, sm, Cm);
}

__global__ void __launch_bounds__(256) add_kernel(float* __restrict__ out)
{
    const size_t i0 = (size_t)blockIdx.x * 512 + threadIdx.x;   // float4 index
#pragma unroll
    for (int r = 0; r < 2; ++r) {
        const size_t i = i0 + r * 256;
        float4 o = ((float4*)out)[i];
        float4 yd = ((const float4*)g_yd)[i];
        o.x += yd.x; o.y += yd.y; o.z += yd.z; o.w += yd.w;
        ((float4*)out)[i] = o;
    }
    if (blockIdx.x == 0 && threadIdx.x == 0) { g_cnt1 = 0u; g_cnt2 = 0u; }
}

extern "C" void kernel_launch(void* const* d_in, const int* in_sizes, int n_in,
                              void* d_out, int out_size)
{
    (void)in_sizes; (void)n_in; (void)out_size;
    const float* X  = (const float*)d_in[0];
    const float* A  = (const float*)d_in[1];
    const float* B  = (const float*)d_in[2];
    const float* C  = (const float*)d_in[3];
    const float* r  = (const float*)d_in[4];
    const float* k  = (const float*)d_in[5];
    const float* v  = (const float*)d_in[6];
    const float* w  = (const float*)d_in[7];
    const float* bo = (const float*)d_in[8];
    float* out = (float*)d_out;

    const int FUSED_SMEM = WKV_SMEM_FLOATS * 4;   // 107072 B
    cudaFuncSetAttribute(fused_kernel,
                         cudaFuncAttributeMaxDynamicSharedMemorySize, FUSED_SMEM);

    fused_kernel<<<1056, 256, FUSED_SMEM>>>(X, A, B, C, r, k, v, w, bo, out);
    add_kernel<<<(2 * 2048 * 1024) / (4 * 512), 256>>>(out);
}